// round 4
// baseline (speedup 1.0000x reference)
#include <cuda_runtime.h>
#include <math.h>

#define BATCH   2
#define SEQ     2048
#define DMODEL  1024
#define NHEADS  16
#define DK      64
#define NQ      (BATCH * SEQ)   // 4096 rows
#define GK      DMODEL          // GEMM K dim (all 4 projections)

// Scratch (allocation-free: device globals)
__device__ float g_q[BATCH * NHEADS * SEQ * DK];   // [b][h][s][d]
__device__ float g_k[BATCH * NHEADS * SEQ * DK];
__device__ float g_v[BATCH * NHEADS * SEQ * DK];
__device__ float g_ctx[NQ * DMODEL];               // [b*S+s][h*64+d]
__device__ float g_cos[SEQ * 32];                  // rope table [s][d/2]
__device__ float g_sin[SEQ * 32];

// ---------------------------------------------------------------------------
// RoPE table: accurate powf/sincosf once, consumed by GEMM epilogues.
// ---------------------------------------------------------------------------
__global__ void rope_table_kernel()
{
    int i = blockIdx.x * 256 + threadIdx.x;   // SEQ*32 = 65536
    int s = i >> 5;
    int j = i & 31;
    float freq = powf(10000.0f, -(float)(2 * j) * (1.0f / 64.0f));
    float sn, cs;
    sincosf((float)s * freq, &sn, &cs);
    g_cos[i] = cs;
    g_sin[i] = sn;
}

// ---------------------------------------------------------------------------
// Shared tf32 helpers
// ---------------------------------------------------------------------------
__device__ __forceinline__ unsigned f2tf(float f)
{
    unsigned u;
    asm("cvt.rna.tf32.f32 %0, %1;" : "=r"(u) : "f"(f));
    return u;
}

__device__ __forceinline__ void mma_tf32(float* d, const unsigned* a, const unsigned* b)
{
    asm volatile(
        "mma.sync.aligned.m16n8k8.row.col.f32.tf32.tf32.f32 "
        "{%0,%1,%2,%3},{%4,%5,%6,%7},{%8,%9},{%0,%1,%2,%3};"
        : "+f"(d[0]), "+f"(d[1]), "+f"(d[2]), "+f"(d[3])
        : "r"(a[0]), "r"(a[1]), "r"(a[2]), "r"(a[3]), "r"(b[0]), "r"(b[1]));
}

// ---------------------------------------------------------------------------
// tf32 tensor-core GEMM: C[M,N] = A[M,K] @ W[N,K]^T
// CTA tile 128x128, 8 warps (2m x 4n), warp tile 64x32, BK=16 double-buffered.
// OUTMODE=0: fused QKV, blockIdx.z selects W/dst; z<2 -> RoPE scatter, z=2 -> plain.
// OUTMODE=1: row-major store (output projection).
// ---------------------------------------------------------------------------
#define BM  128
#define BN  128
#define BKK 16
#define LDP 20    // smem row pitch in words (16 + 4 pad -> conflict-free frags)

__device__ __forceinline__ void sts_tile(unsigned* Abuf, unsigned* Bbuf,
                                         int row0, int kc,
                                         float4 a0, float4 a1,
                                         float4 b0, float4 b1)
{
    uint4 t;
    unsigned* p = Abuf + row0 * LDP + kc;
    t.x = f2tf(a0.x); t.y = f2tf(a0.y); t.z = f2tf(a0.z); t.w = f2tf(a0.w);
    *(uint4*)p = t;
    t.x = f2tf(a1.x); t.y = f2tf(a1.y); t.z = f2tf(a1.z); t.w = f2tf(a1.w);
    *(uint4*)(p + 64 * LDP) = t;
    p = Bbuf + row0 * LDP + kc;
    t.x = f2tf(b0.x); t.y = f2tf(b0.y); t.z = f2tf(b0.z); t.w = f2tf(b0.w);
    *(uint4*)p = t;
    t.x = f2tf(b1.x); t.y = f2tf(b1.y); t.z = f2tf(b1.z); t.w = f2tf(b1.w);
    *(uint4*)(p + 64 * LDP) = t;
}

template <int OUTMODE>
__global__ __launch_bounds__(256) void gemm_kernel(
    const float* __restrict__ A,
    const float* __restrict__ W0,
    const float* __restrict__ W1,
    const float* __restrict__ W2,
    float* __restrict__ D0,
    float* __restrict__ D1,
    float* __restrict__ D2)
{
    __shared__ __align__(16) unsigned As[2][BM * LDP];
    __shared__ __align__(16) unsigned Bs[2][BN * LDP];

    const int z = blockIdx.z;
    const float* W = OUTMODE ? W0 : (z == 0 ? W0 : (z == 1 ? W1 : W2));
    float* dst     = OUTMODE ? D0 : (z == 0 ? D0 : (z == 1 ? D1 : D2));

    const int tid  = threadIdx.x;
    const int lane = tid & 31;
    const int warp = tid >> 5;
    const int wm   = warp & 1;    // 0..1
    const int wn   = warp >> 1;   // 0..3
    const int m0   = blockIdx.y * BM;
    const int n0   = blockIdx.x * BN;

    const int lr = lane >> 2;     // 0..7
    const int lc = lane & 3;      // 0..3

    const int row0 = tid >> 2;           // 0..63
    const int kc   = (tid & 3) * 4;      // 0,4,8,12

    const float* Aptr = A + (m0 + row0) * GK + kc;
    const float* Wptr = W + (n0 + row0) * GK + kc;

    float c[4][4][4];
    #pragma unroll
    for (int i = 0; i < 4; i++)
        #pragma unroll
        for (int j = 0; j < 4; j++)
            #pragma unroll
            for (int r = 0; r < 4; r++)
                c[i][j][r] = 0.f;

    const int NST = GK / BKK;   // 64 stages

    float4 la0 = *(const float4*)Aptr;
    float4 la1 = *(const float4*)(Aptr + 64 * GK);
    float4 lb0 = *(const float4*)Wptr;
    float4 lb1 = *(const float4*)(Wptr + 64 * GK);
    sts_tile(As[0], Bs[0], row0, kc, la0, la1, lb0, lb1);
    __syncthreads();

    for (int s = 0; s < NST; s++) {
        const int cur = s & 1;
        if (s + 1 < NST) {
            const float* ap = Aptr + (s + 1) * BKK;
            const float* wp = Wptr + (s + 1) * BKK;
            la0 = *(const float4*)ap;
            la1 = *(const float4*)(ap + 64 * GK);
            lb0 = *(const float4*)wp;
            lb1 = *(const float4*)(wp + 64 * GK);
        }

        #pragma unroll
        for (int ks = 0; ks < 2; ks++) {
            unsigned af[4][4], bf[4][2];
            #pragma unroll
            for (int mf = 0; mf < 4; mf++) {
                const int m = wm * 64 + mf * 16 + lr;
                const unsigned* p = &As[cur][m * LDP + ks * 8 + lc];
                af[mf][0] = p[0];
                af[mf][1] = p[8 * LDP];
                af[mf][2] = p[4];
                af[mf][3] = p[8 * LDP + 4];
            }
            #pragma unroll
            for (int nf = 0; nf < 4; nf++) {
                const int n = wn * 32 + nf * 8 + lr;
                const unsigned* p = &Bs[cur][n * LDP + ks * 8 + lc];
                bf[nf][0] = p[0];
                bf[nf][1] = p[4];
            }
            #pragma unroll
            for (int mf = 0; mf < 4; mf++)
                #pragma unroll
                for (int nf = 0; nf < 4; nf++)
                    mma_tf32(c[mf][nf], af[mf], bf[nf]);
        }

        if (s + 1 < NST) {
            sts_tile(As[(s + 1) & 1], Bs[(s + 1) & 1], row0, kc, la0, la1, lb0, lb1);
            __syncthreads();
        }
    }

    // Epilogue
    #pragma unroll
    for (int mf = 0; mf < 4; mf++) {
        #pragma unroll
        for (int nf = 0; nf < 4; nf++) {
            const int col = n0 + wn * 32 + nf * 8 + lc * 2;   // even
            #pragma unroll
            for (int half = 0; half < 2; half++) {
                const int r  = m0 + wm * 64 + mf * 16 + lr + half * 8;
                const float v0 = c[mf][nf][half * 2 + 0];
                const float v1 = c[mf][nf][half * 2 + 1];
                if (OUTMODE) {
                    *(float2*)&dst[r * DMODEL + col] = make_float2(v0, v1);
                } else {
                    const int bb = r >> 11;            // / SEQ
                    const int sI = r & (SEQ - 1);
                    const int h  = col >> 6;
                    const int dd = col & 63;           // even
                    const int base = ((bb * NHEADS + h) * SEQ + sI) * DK + dd;
                    if (z < 2) {
                        const float cs = g_cos[sI * 32 + (dd >> 1)];
                        const float sn = g_sin[sI * 32 + (dd >> 1)];
                        *(float2*)&dst[base] =
                            make_float2(v0 * cs - v1 * sn, v0 * sn + v1 * cs);
                    } else {
                        *(float2*)&dst[base] = make_float2(v0, v1);
                    }
                }
            }
        }
    }
}

// ---------------------------------------------------------------------------
// Kernel 2: tensor-core flash attention (tf32 mma), pipelined.
// CTA: 8 warps, 128 queries (16 per warp). Key tiles of 64, double-buffered
// smem, LDG prefetch staged in registers across the compute phases.
// K,V smem [key][d] pitch 68. P round-trips via per-warp smem (tf32).
// ---------------------------------------------------------------------------
#define PIT 68
#define KV_WORDS (64 * PIT)                       // 4352 words per tile buffer
// smem words: K 2 bufs + V 2 bufs + P (8 warps x 16 x PIT)
#define ATTN_SMEM_WORDS (4 * KV_WORDS + 8 * 16 * PIT)
#define ATTN_SMEM_BYTES (ATTN_SMEM_WORDS * 4)

__global__ __launch_bounds__(256, 2) void attn_mma_kernel()
{
    extern __shared__ unsigned sm[];
    // layout: Ks[2] at 0, Vs[2] at 2*KV_WORDS, P at 4*KV_WORDS
    unsigned* Pw = sm + 4 * KV_WORDS + (threadIdx.x >> 5) * 16 * PIT;

    const int tid  = threadIdx.x;
    const int lane = tid & 31;
    const int warp = tid >> 5;
    const int gid  = lane >> 2;   // 0..7
    const int tig  = lane & 3;    // 0..3

    const int h   = blockIdx.y;
    const int b   = blockIdx.z;
    const int qbi = gridDim.x - 1 - blockIdx.x;   // heavy blocks first
    const int q0  = qbi * 128;
    const int ntiles = q0 / 64 + 2;

    const float* kbase = g_k + (size_t)((b * NHEADS + h) * SEQ) * DK;
    const float* vbase = g_v + (size_t)((b * NHEADS + h) * SEQ) * DK;

    // Q fragments (scaled by 1/sqrt(64), tf32). Warp rows q0+warp*16+gid, +8.
    unsigned qf[8][4];
    {
        const float* qp = g_q + (size_t)((b * NHEADS + h) * SEQ + q0 + warp * 16) * DK;
        #pragma unroll
        for (int kc = 0; kc < 8; kc++) {
            qf[kc][0] = f2tf(0.125f * qp[gid * 64 + kc * 8 + tig]);
            qf[kc][1] = f2tf(0.125f * qp[(gid + 8) * 64 + kc * 8 + tig]);
            qf[kc][2] = f2tf(0.125f * qp[gid * 64 + kc * 8 + tig + 4]);
            qf[kc][3] = f2tf(0.125f * qp[(gid + 8) * 64 + kc * 8 + tig + 4]);
        }
    }

    // Staging geometry: 256 threads cover a 64x64 tile; 4 float4 per thread.
    const int skey = tid >> 2;            // 0..63
    const int sc0  = (tid & 3) * 4;       // 0,4,8,12 (+16*i)

    float o[8][4];
    #pragma unroll
    for (int nt = 0; nt < 8; nt++)
        #pragma unroll
        for (int r = 0; r < 4; r++)
            o[nt][r] = 0.f;
    float m0v = -1e30f, m1v = -1e30f, l0 = 0.f, l1 = 0.f;

    float4 st[4];

    // Prologue: tile 0 K and V into buffer 0.
    {
        const float* kp = kbase + (size_t)skey * 64 + sc0;
        #pragma unroll
        for (int i = 0; i < 4; i++) st[i] = *(const float4*)(kp + i * 16);
        unsigned* d = sm + skey * PIT + sc0;
        #pragma unroll
        for (int i = 0; i < 4; i++) {
            uint4 u;
            u.x = f2tf(st[i].x); u.y = f2tf(st[i].y);
            u.z = f2tf(st[i].z); u.w = f2tf(st[i].w);
            *(uint4*)(d + i * 16) = u;
        }
        const float* vp = vbase + (size_t)skey * 64 + sc0;
        #pragma unroll
        for (int i = 0; i < 4; i++) st[i] = *(const float4*)(vp + i * 16);
        d = sm + 2 * KV_WORDS + skey * PIT + sc0;
        #pragma unroll
        for (int i = 0; i < 4; i++) {
            uint4 u;
            u.x = f2tf(st[i].x); u.y = f2tf(st[i].y);
            u.z = f2tf(st[i].z); u.w = f2tf(st[i].w);
            *(uint4*)(d + i * 16) = u;
        }
    }
    __syncthreads();

    for (int kt = 0; kt < ntiles; kt++) {
        const int cur = kt & 1;
        const int nxt = cur ^ 1;
        unsigned* Ksc = sm + cur * KV_WORDS;
        unsigned* Vsc = sm + 2 * KV_WORDS + cur * KV_WORDS;
        const bool have_next = (kt + 1 < ntiles);
        const bool active = (kt * 64 <= q0 + warp * 16 + 15);

        // Prefetch next K tile into registers (latency covered by QK+softmax).
        if (have_next) {
            const float* kp = kbase + (size_t)((kt + 1) * 64 + skey) * 64 + sc0;
            #pragma unroll
            for (int i = 0; i < 4; i++) st[i] = *(const float4*)(kp + i * 16);
        }

        float s[8][4];
        float al0 = 1.f, al1 = 1.f;
        if (active) {
            // S = Q K^T (16 x 64 per warp)
            #pragma unroll
            for (int nt = 0; nt < 8; nt++) {
                s[nt][0] = s[nt][1] = s[nt][2] = s[nt][3] = 0.f;
                #pragma unroll
                for (int kc = 0; kc < 8; kc++) {
                    unsigned bf[2];
                    const unsigned* p = &Ksc[(nt * 8 + gid) * PIT + kc * 8 + tig];
                    bf[0] = p[0];
                    bf[1] = p[4];
                    mma_tf32(s[nt], qf[kc], bf);
                }
            }

            // Causal mask (global indices) on diagonal-region tiles.
            if (kt * 64 + 63 > q0 + warp * 16) {
                const int r0 = q0 + warp * 16 + gid;
                #pragma unroll
                for (int nt = 0; nt < 8; nt++) {
                    const int cg = kt * 64 + nt * 8 + 2 * tig;
                    if (cg > r0)         s[nt][0] = -1e30f;
                    if (cg + 1 > r0)     s[nt][1] = -1e30f;
                    if (cg > r0 + 8)     s[nt][2] = -1e30f;
                    if (cg + 1 > r0 + 8) s[nt][3] = -1e30f;
                }
            }

            // Row max (rows gid and gid+8)
            float mx0 = -1e30f, mx1 = -1e30f;
            #pragma unroll
            for (int nt = 0; nt < 8; nt++) {
                mx0 = fmaxf(mx0, fmaxf(s[nt][0], s[nt][1]));
                mx1 = fmaxf(mx1, fmaxf(s[nt][2], s[nt][3]));
            }
            mx0 = fmaxf(mx0, __shfl_xor_sync(0xffffffffu, mx0, 1));
            mx0 = fmaxf(mx0, __shfl_xor_sync(0xffffffffu, mx0, 2));
            mx1 = fmaxf(mx1, __shfl_xor_sync(0xffffffffu, mx1, 1));
            mx1 = fmaxf(mx1, __shfl_xor_sync(0xffffffffu, mx1, 2));

            const float nm0 = fmaxf(m0v, mx0);
            const float nm1 = fmaxf(m1v, mx1);
            al0 = __expf(m0v - nm0);
            al1 = __expf(m1v - nm1);
            m0v = nm0; m1v = nm1;

            // p = exp(s - m) -> P smem (tf32); accumulate row sums.
            float rs0 = 0.f, rs1 = 0.f;
            #pragma unroll
            for (int nt = 0; nt < 8; nt++) {
                const float p0 = __expf(s[nt][0] - m0v);
                const float p1 = __expf(s[nt][1] - m0v);
                const float p2 = __expf(s[nt][2] - m1v);
                const float p3 = __expf(s[nt][3] - m1v);
                rs0 += p0 + p1;
                rs1 += p2 + p3;
                uint2 w0; w0.x = f2tf(p0); w0.y = f2tf(p1);
                uint2 w1; w1.x = f2tf(p2); w1.y = f2tf(p3);
                *(uint2*)&Pw[gid * PIT + nt * 8 + 2 * tig]       = w0;
                *(uint2*)&Pw[(gid + 8) * PIT + nt * 8 + 2 * tig] = w1;
            }
            rs0 += __shfl_xor_sync(0xffffffffu, rs0, 1);
            rs0 += __shfl_xor_sync(0xffffffffu, rs0, 2);
            rs1 += __shfl_xor_sync(0xffffffffu, rs1, 1);
            rs1 += __shfl_xor_sync(0xffffffffu, rs1, 2);
            l0 = l0 * al0 + rs0;
            l1 = l1 * al1 + rs1;

            // Rescale O
            #pragma unroll
            for (int nt = 0; nt < 8; nt++) {
                o[nt][0] *= al0; o[nt][1] *= al0;
                o[nt][2] *= al1; o[nt][3] *= al1;
            }
        }

        // Store prefetched K into next buffer; then prefetch next V.
        if (have_next) {
            unsigned* d = sm + nxt * KV_WORDS + skey * PIT + sc0;
            #pragma unroll
            for (int i = 0; i < 4; i++) {
                uint4 u;
                u.x = f2tf(st[i].x); u.y = f2tf(st[i].y);
                u.z = f2tf(st[i].z); u.w = f2tf(st[i].w);
                *(uint4*)(d + i * 16) = u;
            }
            const float* vp = vbase + (size_t)((kt + 1) * 64 + skey) * 64 + sc0;
            #pragma unroll
            for (int i = 0; i < 4; i++) st[i] = *(const float4*)(vp + i * 16);
        }

        if (active) {
            __syncwarp();   // P visible across lanes

            // O += P @ V
            #pragma unroll
            for (int kc = 0; kc < 8; kc++) {
                unsigned af[4];
                af[0] = Pw[gid * PIT + kc * 8 + tig];
                af[1] = Pw[(gid + 8) * PIT + kc * 8 + tig];
                af[2] = Pw[gid * PIT + kc * 8 + tig + 4];
                af[3] = Pw[(gid + 8) * PIT + kc * 8 + tig + 4];
                #pragma unroll
                for (int nt = 0; nt < 8; nt++) {
                    unsigned bf[2];
                    const unsigned* p = &Vsc[(kc * 8 + tig) * PIT + nt * 8 + gid];
                    bf[0] = p[0];
                    bf[1] = p[4 * PIT];
                    mma_tf32(o[nt], af, bf);
                }
            }
        }

        // Store prefetched V into next buffer.
        if (have_next) {
            unsigned* d = sm + 2 * KV_WORDS + nxt * KV_WORDS + skey * PIT + sc0;
            #pragma unroll
            for (int i = 0; i < 4; i++) {
                uint4 u;
                u.x = f2tf(st[i].x); u.y = f2tf(st[i].y);
                u.z = f2tf(st[i].z); u.w = f2tf(st[i].w);
                *(uint4*)(d + i * 16) = u;
            }
        }
        __syncthreads();
    }

    // Epilogue: O /= l, scatter to ctx [b*S+q][h*64+d]
    const float il0 = 1.0f / l0;
    const float il1 = 1.0f / l1;
    float* ob = g_ctx + (size_t)(b * SEQ + q0 + warp * 16) * DMODEL + h * 64;
    #pragma unroll
    for (int nt = 0; nt < 8; nt++) {
        const int col = nt * 8 + 2 * tig;
        *(float2*)&ob[gid * DMODEL + col] =
            make_float2(o[nt][0] * il0, o[nt][1] * il0);
        *(float2*)&ob[(gid + 8) * DMODEL + col] =
            make_float2(o[nt][2] * il1, o[nt][3] * il1);
    }
}

// ---------------------------------------------------------------------------
extern "C" void kernel_launch(void* const* d_in, const int* in_sizes, int n_in,
                              void* d_out, int out_size)
{
    const float* x  = (const float*)d_in[0];
    const float* Wq = (const float*)d_in[1];
    const float* Wk = (const float*)d_in[2];
    const float* Wv = (const float*)d_in[3];
    const float* Wo = (const float*)d_in[4];
    float* out = (float*)d_out;

    float* q_p;   cudaGetSymbolAddress((void**)&q_p,   g_q);
    float* k_p;   cudaGetSymbolAddress((void**)&k_p,   g_k);
    float* v_p;   cudaGetSymbolAddress((void**)&v_p,   g_v);
    float* ctx_p; cudaGetSymbolAddress((void**)&ctx_p, g_ctx);

    cudaFuncSetAttribute(attn_mma_kernel,
                         cudaFuncAttributeMaxDynamicSharedMemorySize,
                         ATTN_SMEM_BYTES);

    rope_table_kernel<<<256, 256>>>();

    // Fused QKV projections (z selects Wq/Wk/Wv).
    dim3 gq(DMODEL / BN, NQ / BM, 3);
    gemm_kernel<0><<<gq, 256>>>(x, Wq, Wk, Wv, q_p, k_p, v_p);

    dim3 ga(SEQ / 128, NHEADS, BATCH);
    attn_mma_kernel<<<ga, 256, ATTN_SMEM_BYTES>>>();

    dim3 go(DMODEL / BN, NQ / BM, 1);
    gemm_kernel<1><<<go, 256>>>(ctx_p, Wo, 0, 0, out, 0, 0);
}

// round 5
// speedup vs baseline: 1.0808x; 1.0808x over previous
#include <cuda_runtime.h>
#include <math.h>

#define BATCH   2
#define SEQ     2048
#define DMODEL  1024
#define NHEADS  16
#define DK      64
#define NQ      (BATCH * SEQ)   // 4096 rows
#define GK      DMODEL          // GEMM K dim (all 4 projections)

// Scratch (allocation-free: device globals)
__device__ float g_q[BATCH * NHEADS * SEQ * DK];   // [b][h][s][d]
__device__ float g_k[BATCH * NHEADS * SEQ * DK];
__device__ float g_v[BATCH * NHEADS * SEQ * DK];
__device__ float g_ctx[NQ * DMODEL];               // [b*S+s][h*64+d]
__device__ float g_cos[SEQ * 32];                  // rope table [s][d/2]
__device__ float g_sin[SEQ * 32];

// ---------------------------------------------------------------------------
// RoPE table: accurate powf/sincosf once, consumed by GEMM epilogues.
// ---------------------------------------------------------------------------
__global__ void rope_table_kernel()
{
    int i = blockIdx.x * 256 + threadIdx.x;   // SEQ*32 = 65536
    int s = i >> 5;
    int j = i & 31;
    float freq = powf(10000.0f, -(float)(2 * j) * (1.0f / 64.0f));
    float sn, cs;
    sincosf((float)s * freq, &sn, &cs);
    g_cos[i] = cs;
    g_sin[i] = sn;
}

// ---------------------------------------------------------------------------
// Shared tf32 helpers
// ---------------------------------------------------------------------------
__device__ __forceinline__ unsigned f2tf(float f)
{
    unsigned u;
    asm("cvt.rna.tf32.f32 %0, %1;" : "=r"(u) : "f"(f));
    return u;
}

__device__ __forceinline__ void mma_tf32(float* d, const unsigned* a, const unsigned* b)
{
    asm volatile(
        "mma.sync.aligned.m16n8k8.row.col.f32.tf32.tf32.f32 "
        "{%0,%1,%2,%3},{%4,%5,%6,%7},{%8,%9},{%0,%1,%2,%3};"
        : "+f"(d[0]), "+f"(d[1]), "+f"(d[2]), "+f"(d[3])
        : "r"(a[0]), "r"(a[1]), "r"(a[2]), "r"(a[3]), "r"(b[0]), "r"(b[1]));
}

// ---------------------------------------------------------------------------
// tf32 tensor-core GEMM: C[M,N] = A[M,K] @ W[N,K]^T
// CTA tile 128x128, 8 warps (2m x 4n), warp tile 64x32, BK=16 double-buffered.
// OUTMODE=0: fused QKV, blockIdx.z selects W/dst; z<2 -> RoPE scatter, z=2 -> plain.
// OUTMODE=1: row-major store (output projection).
// ---------------------------------------------------------------------------
#define BM  128
#define BN  128
#define BKK 16
#define LDP 20    // smem row pitch in words (16 + 4 pad -> conflict-free frags)

__device__ __forceinline__ void sts_tile(unsigned* Abuf, unsigned* Bbuf,
                                         int row0, int kc,
                                         float4 a0, float4 a1,
                                         float4 b0, float4 b1)
{
    uint4 t;
    unsigned* p = Abuf + row0 * LDP + kc;
    t.x = f2tf(a0.x); t.y = f2tf(a0.y); t.z = f2tf(a0.z); t.w = f2tf(a0.w);
    *(uint4*)p = t;
    t.x = f2tf(a1.x); t.y = f2tf(a1.y); t.z = f2tf(a1.z); t.w = f2tf(a1.w);
    *(uint4*)(p + 64 * LDP) = t;
    p = Bbuf + row0 * LDP + kc;
    t.x = f2tf(b0.x); t.y = f2tf(b0.y); t.z = f2tf(b0.z); t.w = f2tf(b0.w);
    *(uint4*)p = t;
    t.x = f2tf(b1.x); t.y = f2tf(b1.y); t.z = f2tf(b1.z); t.w = f2tf(b1.w);
    *(uint4*)(p + 64 * LDP) = t;
}

template <int OUTMODE>
__global__ __launch_bounds__(256) void gemm_kernel(
    const float* __restrict__ A,
    const float* __restrict__ W0,
    const float* __restrict__ W1,
    const float* __restrict__ W2,
    float* __restrict__ D0,
    float* __restrict__ D1,
    float* __restrict__ D2)
{
    __shared__ __align__(16) unsigned As[2][BM * LDP];
    __shared__ __align__(16) unsigned Bs[2][BN * LDP];

    const int z = blockIdx.z;
    const float* W = OUTMODE ? W0 : (z == 0 ? W0 : (z == 1 ? W1 : W2));
    float* dst     = OUTMODE ? D0 : (z == 0 ? D0 : (z == 1 ? D1 : D2));

    const int tid  = threadIdx.x;
    const int lane = tid & 31;
    const int warp = tid >> 5;
    const int wm   = warp & 1;    // 0..1
    const int wn   = warp >> 1;   // 0..3
    const int m0   = blockIdx.y * BM;
    const int n0   = blockIdx.x * BN;

    const int lr = lane >> 2;     // 0..7
    const int lc = lane & 3;      // 0..3

    const int row0 = tid >> 2;           // 0..63
    const int kc   = (tid & 3) * 4;      // 0,4,8,12

    const float* Aptr = A + (m0 + row0) * GK + kc;
    const float* Wptr = W + (n0 + row0) * GK + kc;

    float c[4][4][4];
    #pragma unroll
    for (int i = 0; i < 4; i++)
        #pragma unroll
        for (int j = 0; j < 4; j++)
            #pragma unroll
            for (int r = 0; r < 4; r++)
                c[i][j][r] = 0.f;

    const int NST = GK / BKK;   // 64 stages

    float4 la0 = *(const float4*)Aptr;
    float4 la1 = *(const float4*)(Aptr + 64 * GK);
    float4 lb0 = *(const float4*)Wptr;
    float4 lb1 = *(const float4*)(Wptr + 64 * GK);
    sts_tile(As[0], Bs[0], row0, kc, la0, la1, lb0, lb1);
    __syncthreads();

    for (int s = 0; s < NST; s++) {
        const int cur = s & 1;
        if (s + 1 < NST) {
            const float* ap = Aptr + (s + 1) * BKK;
            const float* wp = Wptr + (s + 1) * BKK;
            la0 = *(const float4*)ap;
            la1 = *(const float4*)(ap + 64 * GK);
            lb0 = *(const float4*)wp;
            lb1 = *(const float4*)(wp + 64 * GK);
        }

        #pragma unroll
        for (int ks = 0; ks < 2; ks++) {
            unsigned af[4][4], bf[4][2];
            #pragma unroll
            for (int mf = 0; mf < 4; mf++) {
                const int m = wm * 64 + mf * 16 + lr;
                const unsigned* p = &As[cur][m * LDP + ks * 8 + lc];
                af[mf][0] = p[0];
                af[mf][1] = p[8 * LDP];
                af[mf][2] = p[4];
                af[mf][3] = p[8 * LDP + 4];
            }
            #pragma unroll
            for (int nf = 0; nf < 4; nf++) {
                const int n = wn * 32 + nf * 8 + lr;
                const unsigned* p = &Bs[cur][n * LDP + ks * 8 + lc];
                bf[nf][0] = p[0];
                bf[nf][1] = p[4];
            }
            #pragma unroll
            for (int mf = 0; mf < 4; mf++)
                #pragma unroll
                for (int nf = 0; nf < 4; nf++)
                    mma_tf32(c[mf][nf], af[mf], bf[nf]);
        }

        if (s + 1 < NST) {
            sts_tile(As[(s + 1) & 1], Bs[(s + 1) & 1], row0, kc, la0, la1, lb0, lb1);
            __syncthreads();
        }
    }

    // Epilogue
    #pragma unroll
    for (int mf = 0; mf < 4; mf++) {
        #pragma unroll
        for (int nf = 0; nf < 4; nf++) {
            const int col = n0 + wn * 32 + nf * 8 + lc * 2;   // even
            #pragma unroll
            for (int half = 0; half < 2; half++) {
                const int r  = m0 + wm * 64 + mf * 16 + lr + half * 8;
                const float v0 = c[mf][nf][half * 2 + 0];
                const float v1 = c[mf][nf][half * 2 + 1];
                if (OUTMODE) {
                    *(float2*)&dst[r * DMODEL + col] = make_float2(v0, v1);
                } else {
                    const int bb = r >> 11;            // / SEQ
                    const int sI = r & (SEQ - 1);
                    const int h  = col >> 6;
                    const int dd = col & 63;           // even
                    const int base = ((bb * NHEADS + h) * SEQ + sI) * DK + dd;
                    if (z < 2) {
                        const float cs = g_cos[sI * 32 + (dd >> 1)];
                        const float sn = g_sin[sI * 32 + (dd >> 1)];
                        *(float2*)&dst[base] =
                            make_float2(v0 * cs - v1 * sn, v0 * sn + v1 * cs);
                    } else {
                        *(float2*)&dst[base] = make_float2(v0, v1);
                    }
                }
            }
        }
    }
}

// ---------------------------------------------------------------------------
// Kernel 2: tensor-core flash attention (tf32 mma) — proven R3 version.
// CTA: 4 warps, 64 queries (16 per warp). Key tiles of 64.
// K,V in smem [key][d] pitch 68 (conflict-free B-frags for QK; ~2-way for PV).
// P round-trips through per-warp smem to convert C-layout -> A-layout.
// 52 KB smem -> 4 CTAs/SM; occupancy does the latency hiding.
// ---------------------------------------------------------------------------
#define PIT 68
// smem words: Ks 64*68, Vs 64*68, P 4*16*68  = 13056 words = 52224 bytes
#define ATTN_SMEM_BYTES ((64 * PIT * 2 + 4 * 16 * PIT) * 4)

__global__ __launch_bounds__(128) void attn_mma_kernel()
{
    extern __shared__ unsigned sm[];
    unsigned* Ks = sm;                     // [key][d]
    unsigned* Vs = sm + 64 * PIT;          // [key][d]
    unsigned* Pw = sm + 2 * 64 * PIT + (threadIdx.x >> 5) * 16 * PIT;

    const int tid  = threadIdx.x;
    const int lane = tid & 31;
    const int warp = tid >> 5;
    const int gid  = lane >> 2;   // 0..7
    const int tig  = lane & 3;    // 0..3

    const int h  = blockIdx.y;
    const int b  = blockIdx.z;
    const int qb = gridDim.x - 1 - blockIdx.x;   // heavy blocks first
    const int q0 = qb * 64;

    const float* kbase = g_k + (size_t)((b * NHEADS + h) * SEQ) * DK;
    const float* vbase = g_v + (size_t)((b * NHEADS + h) * SEQ) * DK;
    const float* qbase = g_q + (size_t)((b * NHEADS + h) * SEQ + q0) * DK;

    // Q fragments (scaled by 1/sqrt(64), tf32). Rows warp*16+gid, +8.
    unsigned qf[8][4];
    {
        const int r0 = warp * 16 + gid;
        #pragma unroll
        for (int kc = 0; kc < 8; kc++) {
            qf[kc][0] = f2tf(0.125f * qbase[r0 * 64 + kc * 8 + tig]);
            qf[kc][1] = f2tf(0.125f * qbase[(r0 + 8) * 64 + kc * 8 + tig]);
            qf[kc][2] = f2tf(0.125f * qbase[r0 * 64 + kc * 8 + tig + 4]);
            qf[kc][3] = f2tf(0.125f * qbase[(r0 + 8) * 64 + kc * 8 + tig + 4]);
        }
    }

    float o[8][4];
    #pragma unroll
    for (int nt = 0; nt < 8; nt++)
        #pragma unroll
        for (int r = 0; r < 4; r++)
            o[nt][r] = 0.f;
    float m0v = -1e30f, m1v = -1e30f, l0 = 0.f, l1 = 0.f;

    const int ntiles = qb + 1;
    for (int kt = 0; kt < ntiles; kt++) {
        __syncthreads();   // previous-tile smem reads complete
        #pragma unroll
        for (int i = 0; i < 8; i++) {
            const int idx = i * 128 + tid;
            const int key = idx >> 4;
            const int c4  = (idx & 15) * 4;
            float4 kv = *(const float4*)&kbase[(size_t)(kt * 64 + key) * 64 + c4];
            float4 vv = *(const float4*)&vbase[(size_t)(kt * 64 + key) * 64 + c4];
            uint4 u;
            u.x = f2tf(kv.x); u.y = f2tf(kv.y); u.z = f2tf(kv.z); u.w = f2tf(kv.w);
            *(uint4*)&Ks[key * PIT + c4] = u;
            u.x = f2tf(vv.x); u.y = f2tf(vv.y); u.z = f2tf(vv.z); u.w = f2tf(vv.w);
            *(uint4*)&Vs[key * PIT + c4] = u;
        }
        __syncthreads();

        // S = Q K^T (16 x 64 per warp)
        float s[8][4];
        #pragma unroll
        for (int nt = 0; nt < 8; nt++) {
            s[nt][0] = s[nt][1] = s[nt][2] = s[nt][3] = 0.f;
            #pragma unroll
            for (int kc = 0; kc < 8; kc++) {
                unsigned bf[2];
                const unsigned* p = &Ks[(nt * 8 + gid) * PIT + kc * 8 + tig];
                bf[0] = p[0];
                bf[1] = p[4];
                mma_tf32(s[nt], qf[kc], bf);
            }
        }

        // Causal mask on diagonal tile
        if (kt == qb) {
            const int r0 = warp * 16 + gid;
            #pragma unroll
            for (int nt = 0; nt < 8; nt++) {
                const int c = nt * 8 + 2 * tig;
                if (c > r0)         s[nt][0] = -1e30f;
                if (c + 1 > r0)     s[nt][1] = -1e30f;
                if (c > r0 + 8)     s[nt][2] = -1e30f;
                if (c + 1 > r0 + 8) s[nt][3] = -1e30f;
            }
        }

        // Row max (rows gid and gid+8)
        float mx0 = -1e30f, mx1 = -1e30f;
        #pragma unroll
        for (int nt = 0; nt < 8; nt++) {
            mx0 = fmaxf(mx0, fmaxf(s[nt][0], s[nt][1]));
            mx1 = fmaxf(mx1, fmaxf(s[nt][2], s[nt][3]));
        }
        mx0 = fmaxf(mx0, __shfl_xor_sync(0xffffffffu, mx0, 1));
        mx0 = fmaxf(mx0, __shfl_xor_sync(0xffffffffu, mx0, 2));
        mx1 = fmaxf(mx1, __shfl_xor_sync(0xffffffffu, mx1, 1));
        mx1 = fmaxf(mx1, __shfl_xor_sync(0xffffffffu, mx1, 2));

        const float nm0 = fmaxf(m0v, mx0);
        const float nm1 = fmaxf(m1v, mx1);
        const float al0 = __expf(m0v - nm0);
        const float al1 = __expf(m1v - nm1);
        m0v = nm0; m1v = nm1;

        // p = exp(s - m); write to P smem (tf32); accumulate row sums
        float rs0 = 0.f, rs1 = 0.f;
        #pragma unroll
        for (int nt = 0; nt < 8; nt++) {
            const float p0 = __expf(s[nt][0] - m0v);
            const float p1 = __expf(s[nt][1] - m0v);
            const float p2 = __expf(s[nt][2] - m1v);
            const float p3 = __expf(s[nt][3] - m1v);
            rs0 += p0 + p1;
            rs1 += p2 + p3;
            uint2 w0; w0.x = f2tf(p0); w0.y = f2tf(p1);
            uint2 w1; w1.x = f2tf(p2); w1.y = f2tf(p3);
            *(uint2*)&Pw[gid * PIT + nt * 8 + 2 * tig]       = w0;
            *(uint2*)&Pw[(gid + 8) * PIT + nt * 8 + 2 * tig] = w1;
        }
        rs0 += __shfl_xor_sync(0xffffffffu, rs0, 1);
        rs0 += __shfl_xor_sync(0xffffffffu, rs0, 2);
        rs1 += __shfl_xor_sync(0xffffffffu, rs1, 1);
        rs1 += __shfl_xor_sync(0xffffffffu, rs1, 2);
        l0 = l0 * al0 + rs0;
        l1 = l1 * al1 + rs1;

        // Rescale O
        #pragma unroll
        for (int nt = 0; nt < 8; nt++) {
            o[nt][0] *= al0; o[nt][1] *= al0;
            o[nt][2] *= al1; o[nt][3] *= al1;
        }

        __syncwarp();   // P visible across lanes

        // O += P @ V
        #pragma unroll
        for (int kc = 0; kc < 8; kc++) {
            unsigned af[4];
            af[0] = Pw[gid * PIT + kc * 8 + tig];
            af[1] = Pw[(gid + 8) * PIT + kc * 8 + tig];
            af[2] = Pw[gid * PIT + kc * 8 + tig + 4];
            af[3] = Pw[(gid + 8) * PIT + kc * 8 + tig + 4];
            #pragma unroll
            for (int nt = 0; nt < 8; nt++) {
                unsigned bf[2];
                const unsigned* p = &Vs[(kc * 8 + tig) * PIT + nt * 8 + gid];
                bf[0] = p[0];
                bf[1] = p[4 * PIT];
                mma_tf32(o[nt], af, bf);
            }
        }
    }

    // Epilogue: O /= l, scatter to ctx [b*S+q][h*64+d]
    const float il0 = 1.0f / l0;
    const float il1 = 1.0f / l1;
    float* ob = g_ctx + (size_t)(b * SEQ + q0 + warp * 16) * DMODEL + h * 64;
    #pragma unroll
    for (int nt = 0; nt < 8; nt++) {
        const int col = nt * 8 + 2 * tig;
        *(float2*)&ob[gid * DMODEL + col] =
            make_float2(o[nt][0] * il0, o[nt][1] * il0);
        *(float2*)&ob[(gid + 8) * DMODEL + col] =
            make_float2(o[nt][2] * il1, o[nt][3] * il1);
    }
}

// ---------------------------------------------------------------------------
extern "C" void kernel_launch(void* const* d_in, const int* in_sizes, int n_in,
                              void* d_out, int out_size)
{
    const float* x  = (const float*)d_in[0];
    const float* Wq = (const float*)d_in[1];
    const float* Wk = (const float*)d_in[2];
    const float* Wv = (const float*)d_in[3];
    const float* Wo = (const float*)d_in[4];
    float* out = (float*)d_out;

    float* q_p;   cudaGetSymbolAddress((void**)&q_p,   g_q);
    float* k_p;   cudaGetSymbolAddress((void**)&k_p,   g_k);
    float* v_p;   cudaGetSymbolAddress((void**)&v_p,   g_v);
    float* ctx_p; cudaGetSymbolAddress((void**)&ctx_p, g_ctx);

    cudaFuncSetAttribute(attn_mma_kernel,
                         cudaFuncAttributeMaxDynamicSharedMemorySize,
                         ATTN_SMEM_BYTES);

    rope_table_kernel<<<256, 256>>>();

    // Fused QKV projections (z selects Wq/Wk/Wv).
    dim3 gq(DMODEL / BN, NQ / BM, 3);
    gemm_kernel<0><<<gq, 256>>>(x, Wq, Wk, Wv, q_p, k_p, v_p);

    dim3 ga(SEQ / 64, NHEADS, BATCH);
    attn_mma_kernel<<<ga, 128, ATTN_SMEM_BYTES>>>();

    dim3 go(DMODEL / BN, NQ / BM, 1);
    gemm_kernel<1><<<go, 256>>>(ctx_p, Wo, 0, 0, out, 0, 0);
}

// round 7
// speedup vs baseline: 1.0816x; 1.0008x over previous
#include <cuda_runtime.h>
#include <stdint.h>
#include <math.h>

#define BATCH   2
#define SEQ     2048
#define DMODEL  1024
#define NHEADS  16
#define DK      64
#define NQ      (BATCH * SEQ)   // 4096 rows
#define GK      DMODEL          // GEMM K dim (all 4 projections)

// Scratch (allocation-free: device globals)
__device__ float g_q[BATCH * NHEADS * SEQ * DK];   // [b][h][s][d]
__device__ float g_k[BATCH * NHEADS * SEQ * DK];
__device__ float g_v[BATCH * NHEADS * SEQ * DK];
__device__ float g_ctx[NQ * DMODEL];               // [b*S+s][h*64+d]
__device__ float g_cos[SEQ * 32];                  // rope table [s][d/2]
__device__ float g_sin[SEQ * 32];

// ---------------------------------------------------------------------------
// RoPE table
// ---------------------------------------------------------------------------
__global__ void rope_table_kernel()
{
    int i = blockIdx.x * 256 + threadIdx.x;   // SEQ*32 = 65536
    int s = i >> 5;
    int j = i & 31;
    float freq = powf(10000.0f, -(float)(2 * j) * (1.0f / 64.0f));
    float sn, cs;
    sincosf((float)s * freq, &sn, &cs);
    g_cos[i] = cs;
    g_sin[i] = sn;
}

// ---------------------------------------------------------------------------
// Shared tf32 helpers
// ---------------------------------------------------------------------------
__device__ __forceinline__ unsigned f2tf(float f)
{
    unsigned u;
    asm("cvt.rna.tf32.f32 %0, %1;" : "=r"(u) : "f"(f));
    return u;
}

__device__ __forceinline__ void mma_tf32(float* d, const unsigned* a, const unsigned* b)
{
    asm volatile(
        "mma.sync.aligned.m16n8k8.row.col.f32.tf32.tf32.f32 "
        "{%0,%1,%2,%3},{%4,%5,%6,%7},{%8,%9},{%0,%1,%2,%3};"
        : "+f"(d[0]), "+f"(d[1]), "+f"(d[2]), "+f"(d[3])
        : "r"(a[0]), "r"(a[1]), "r"(a[2]), "r"(a[3]), "r"(b[0]), "r"(b[1]));
}

// ---------------------------------------------------------------------------
// tf32 tensor-core GEMM: C[M,N] = A[M,K] @ W[N,K]^T
// CTA tile 128x128, 8 warps (2m x 4n), warp tile 64x32, BK=16 double-buffered.
//
// Fragment-ready smem layout (this round's change):
//   A frags: [buf][ks(2)][mtile(8)][lane(32)][reg(4)]  (2048 words/buf)
//   B frags: [buf][ks(2)][ntile(16)][lane(32)][reg(2)] (2048 words/buf)
// A lane slot XOR-swizzled by (ks ^ 2*(mtile&1)), B pair slot by ks, so both
// the vectorized STS.128 staging stores and the LDS.128/LDS.64 fragment loads
// hit the 4-/2-phase crossbar floor with zero conflicts.
//
// mma fragment maps (verified by passing R5 kernel):
//   A (m16k8): lane=(m%8)*4+(k%4), reg=(m%16)/8 + 2*((k%8)/4)
//   B (k8n8):  lane=(n%8)*4+(k%4), reg=(k%8)/4
//
// OUTMODE=0: fused QKV (z selects W/dst; z<2 RoPE scatter, z=2 plain scatter)
// OUTMODE=1: row-major store
// ---------------------------------------------------------------------------
#define BM  128
#define BN  128
#define BKK 16

template <int OUTMODE>
__global__ __launch_bounds__(256) void gemm_kernel(
    const float* __restrict__ A,
    const float* __restrict__ W0,
    const float* __restrict__ W1,
    const float* __restrict__ W2,
    float* __restrict__ D0,
    float* __restrict__ D1,
    float* __restrict__ D2)
{
    __shared__ __align__(16) unsigned Sg[8192];   // 32 KB: A[2][2048] | B[2][2048]

    const int z = blockIdx.z;
    const float* W = OUTMODE ? W0 : (z == 0 ? W0 : (z == 1 ? W1 : W2));
    float* dst     = OUTMODE ? D0 : (z == 0 ? D0 : (z == 1 ? D1 : D2));

    const int tid  = threadIdx.x;
    const int lane = tid & 31;
    const int warp = tid >> 5;
    const int wm   = warp & 1;    // 0..1
    const int wn   = warp >> 1;   // 0..3
    const int m0   = blockIdx.y * BM;
    const int n0   = blockIdx.x * BN;

    // ---- staging role: threads 0-127 stage A, 128-255 stage B ----
    const bool isA = tid < 128;
    const int t    = isA ? tid : tid - 128;
    const int ksS  = t & 1;            // which K=8 slab of the stage
    const int pS   = t >> 1;           // 0..63
    const int mtileS = pS >> 3;        // A: 0..7
    const int mrS    = pS & 7;
    const int swzA   = ksS ^ ((mtileS & 1) << 1);

    const float* g0;
    const float* g1;
    if (isA) {
        const int r = m0 + mtileS * 16 + mrS;
        g0 = A + (size_t)r * GK + ksS * 8;     // rows r and r+8
        g1 = g0 + (size_t)8 * GK;
    } else {
        const int r = n0 + pS;
        g0 = W + (size_t)r * GK + ksS * 8;     // rows r and r+64
        g1 = g0 + (size_t)64 * GK;
    }

    float c[4][4][4];
    #pragma unroll
    for (int i = 0; i < 4; i++)
        #pragma unroll
        for (int j = 0; j < 4; j++)
            #pragma unroll
            for (int r = 0; r < 4; r++)
                c[i][j][r] = 0.f;

    float4 v0, v1, v2, v3;   // staging regs: {row0 k0..3, row0 k4..7, row1 k0..3, row1 k4..7}

    // store staged regs (tf32-converted) into fragment layout, buffer `buf`
    auto stage_store = [&](int buf) {
        const float* f0 = (const float*)&v0;
        const float* f1 = (const float*)&v1;
        const float* f2 = (const float*)&v2;
        const float* f3 = (const float*)&v3;
        if (isA) {
            unsigned* base = Sg + buf * 2048 + ksS * 1024 + mtileS * 128;
            #pragma unroll
            for (int j = 0; j < 4; j++) {
                const int jj = j ^ swzA;
                uint4 u;
                u.x = f2tf(f0[j]); u.y = f2tf(f2[j]);   // regs 0,1: rows m, m+8 @ k=j
                u.z = f2tf(f1[j]); u.w = f2tf(f3[j]);   // regs 2,3: rows m, m+8 @ k=j+4
                *(uint4*)(base + (mrS * 4 + jj) * 4) = u;
            }
        } else {
            unsigned* b0 = Sg + 4096 + buf * 2048 + ksS * 1024 + (pS >> 3) * 64 + (pS & 7) * 8;
            unsigned* b1 = b0 + 8 * 64;   // row +64 -> ntile +8
            #pragma unroll
            for (int i = 0; i < 2; i++) {
                const int ii = i ^ ksS;
                uint4 u;
                u.x = f2tf(f0[2 * i]);     u.y = f2tf(f1[2 * i]);      // lane 4q+2i: regs 0,1
                u.z = f2tf(f0[2 * i + 1]); u.w = f2tf(f1[2 * i + 1]);  // lane 4q+2i+1
                *(uint4*)(b0 + ii * 4) = u;
                u.x = f2tf(f2[2 * i]);     u.y = f2tf(f3[2 * i]);
                u.z = f2tf(f2[2 * i + 1]); u.w = f2tf(f3[2 * i + 1]);
                *(uint4*)(b1 + ii * 4) = u;
            }
        }
    };

    const int NST = GK / BKK;   // 64 stages

    // Prologue: stage 0 -> buffer 0
    v0 = *(const float4*)g0;
    v1 = *(const float4*)(g0 + 4);
    v2 = *(const float4*)g1;
    v3 = *(const float4*)(g1 + 4);
    stage_store(0);
    __syncthreads();

    const int q = lane >> 2;
    const int j = lane & 3;

    for (int s = 0; s < NST; s++) {
        const int cur = s & 1;
        if (s + 1 < NST) {
            const float* p0 = g0 + (s + 1) * BKK;
            const float* p1 = g1 + (s + 1) * BKK;
            v0 = *(const float4*)p0;
            v1 = *(const float4*)(p0 + 4);
            v2 = *(const float4*)p1;
            v3 = *(const float4*)(p1 + 4);
        }

        #pragma unroll
        for (int ks = 0; ks < 2; ks++) {
            unsigned af[4][4], bf[4][2];
            #pragma unroll
            for (int mf = 0; mf < 4; mf++) {
                const int mtg = wm * 4 + mf;
                const int jA  = j ^ ks ^ ((mtg & 1) << 1);
                const uint4 u = *(const uint4*)(Sg + cur * 2048 + ks * 1024 +
                                                mtg * 128 + (q * 4 + jA) * 4);
                af[mf][0] = u.x; af[mf][1] = u.y; af[mf][2] = u.z; af[mf][3] = u.w;
            }
            #pragma unroll
            for (int nf = 0; nf < 4; nf++) {
                const int ntg = wn * 4 + nf;
                const uint2 u = *(const uint2*)(Sg + 4096 + cur * 2048 + ks * 1024 +
                                                ntg * 64 + q * 8 +
                                                (((j >> 1) ^ ks) * 4) + (j & 1) * 2);
                bf[nf][0] = u.x; bf[nf][1] = u.y;
            }
            #pragma unroll
            for (int mf = 0; mf < 4; mf++)
                #pragma unroll
                for (int nf = 0; nf < 4; nf++)
                    mma_tf32(c[mf][nf], af[mf], bf[nf]);
        }

        if (s + 1 < NST) stage_store(cur ^ 1);
        __syncthreads();
    }

    // Epilogue (identical to R5)
    const int lr = lane >> 2;
    const int lc = lane & 3;
    #pragma unroll
    for (int mf = 0; mf < 4; mf++) {
        #pragma unroll
        for (int nf = 0; nf < 4; nf++) {
            const int col = n0 + wn * 32 + nf * 8 + lc * 2;   // even
            #pragma unroll
            for (int half = 0; half < 2; half++) {
                const int r  = m0 + wm * 64 + mf * 16 + lr + half * 8;
                const float x0 = c[mf][nf][half * 2 + 0];
                const float x1 = c[mf][nf][half * 2 + 1];
                if (OUTMODE) {
                    *(float2*)&dst[(size_t)r * DMODEL + col] = make_float2(x0, x1);
                } else {
                    const int bb = r >> 11;            // / SEQ
                    const int sI = r & (SEQ - 1);
                    const int h  = col >> 6;
                    const int dd = col & 63;           // even
                    const int base = ((bb * NHEADS + h) * SEQ + sI) * DK + dd;
                    if (z < 2) {
                        const float cs = g_cos[sI * 32 + (dd >> 1)];
                        const float sn = g_sin[sI * 32 + (dd >> 1)];
                        *(float2*)&dst[base] =
                            make_float2(x0 * cs - x1 * sn, x0 * sn + x1 * cs);
                    } else {
                        *(float2*)&dst[base] = make_float2(x0, x1);
                    }
                }
            }
        }
    }
}

// ---------------------------------------------------------------------------
// Kernel 2: tensor-core flash attention (tf32 mma.sync) — proven R3/R5 version.
// ---------------------------------------------------------------------------
#define PIT 68
#define ATTN_SMEM_BYTES ((64 * PIT * 2 + 4 * 16 * PIT) * 4)

__global__ __launch_bounds__(128) void attn_mma_kernel()
{
    extern __shared__ unsigned sm[];
    unsigned* Ks = sm;                     // [key][d]
    unsigned* Vs = sm + 64 * PIT;          // [key][d]
    unsigned* Pw = sm + 2 * 64 * PIT + (threadIdx.x >> 5) * 16 * PIT;

    const int tid  = threadIdx.x;
    const int lane = tid & 31;
    const int warp = tid >> 5;
    const int gid  = lane >> 2;   // 0..7
    const int tig  = lane & 3;    // 0..3

    const int h  = blockIdx.y;
    const int b  = blockIdx.z;
    const int qb = gridDim.x - 1 - blockIdx.x;   // heavy blocks first
    const int q0 = qb * 64;

    const float* kbase = g_k + (size_t)((b * NHEADS + h) * SEQ) * DK;
    const float* vbase = g_v + (size_t)((b * NHEADS + h) * SEQ) * DK;
    const float* qbase = g_q + (size_t)((b * NHEADS + h) * SEQ + q0) * DK;

    unsigned qf[8][4];
    {
        const int r0 = warp * 16 + gid;
        #pragma unroll
        for (int kc = 0; kc < 8; kc++) {
            qf[kc][0] = f2tf(0.125f * qbase[r0 * 64 + kc * 8 + tig]);
            qf[kc][1] = f2tf(0.125f * qbase[(r0 + 8) * 64 + kc * 8 + tig]);
            qf[kc][2] = f2tf(0.125f * qbase[r0 * 64 + kc * 8 + tig + 4]);
            qf[kc][3] = f2tf(0.125f * qbase[(r0 + 8) * 64 + kc * 8 + tig + 4]);
        }
    }

    float o[8][4];
    #pragma unroll
    for (int nt = 0; nt < 8; nt++)
        #pragma unroll
        for (int r = 0; r < 4; r++)
            o[nt][r] = 0.f;
    float m0v = -1e30f, m1v = -1e30f, l0 = 0.f, l1 = 0.f;

    const int ntiles = qb + 1;
    for (int kt = 0; kt < ntiles; kt++) {
        __syncthreads();
        #pragma unroll
        for (int i = 0; i < 8; i++) {
            const int idx = i * 128 + tid;
            const int key = idx >> 4;
            const int c4  = (idx & 15) * 4;
            float4 kv = *(const float4*)&kbase[(size_t)(kt * 64 + key) * 64 + c4];
            float4 vv = *(const float4*)&vbase[(size_t)(kt * 64 + key) * 64 + c4];
            uint4 u;
            u.x = f2tf(kv.x); u.y = f2tf(kv.y); u.z = f2tf(kv.z); u.w = f2tf(kv.w);
            *(uint4*)&Ks[key * PIT + c4] = u;
            u.x = f2tf(vv.x); u.y = f2tf(vv.y); u.z = f2tf(vv.z); u.w = f2tf(vv.w);
            *(uint4*)&Vs[key * PIT + c4] = u;
        }
        __syncthreads();

        float s[8][4];
        #pragma unroll
        for (int nt = 0; nt < 8; nt++) {
            s[nt][0] = s[nt][1] = s[nt][2] = s[nt][3] = 0.f;
            #pragma unroll
            for (int kc = 0; kc < 8; kc++) {
                unsigned bfv[2];
                const unsigned* p = &Ks[(nt * 8 + gid) * PIT + kc * 8 + tig];
                bfv[0] = p[0];
                bfv[1] = p[4];
                mma_tf32(s[nt], qf[kc], bfv);
            }
        }

        if (kt == qb) {
            const int r0 = warp * 16 + gid;
            #pragma unroll
            for (int nt = 0; nt < 8; nt++) {
                const int c = nt * 8 + 2 * tig;
                if (c > r0)         s[nt][0] = -1e30f;
                if (c + 1 > r0)     s[nt][1] = -1e30f;
                if (c > r0 + 8)     s[nt][2] = -1e30f;
                if (c + 1 > r0 + 8) s[nt][3] = -1e30f;
            }
        }

        float mx0 = -1e30f, mx1 = -1e30f;
        #pragma unroll
        for (int nt = 0; nt < 8; nt++) {
            mx0 = fmaxf(mx0, fmaxf(s[nt][0], s[nt][1]));
            mx1 = fmaxf(mx1, fmaxf(s[nt][2], s[nt][3]));
        }
        mx0 = fmaxf(mx0, __shfl_xor_sync(0xffffffffu, mx0, 1));
        mx0 = fmaxf(mx0, __shfl_xor_sync(0xffffffffu, mx0, 2));
        mx1 = fmaxf(mx1, __shfl_xor_sync(0xffffffffu, mx1, 1));
        mx1 = fmaxf(mx1, __shfl_xor_sync(0xffffffffu, mx1, 2));

        const float nm0 = fmaxf(m0v, mx0);
        const float nm1 = fmaxf(m1v, mx1);
        const float al0 = __expf(m0v - nm0);
        const float al1 = __expf(m1v - nm1);
        m0v = nm0; m1v = nm1;

        float rs0 = 0.f, rs1 = 0.f;
        #pragma unroll
        for (int nt = 0; nt < 8; nt++) {
            const float p0 = __expf(s[nt][0] - m0v);
            const float p1 = __expf(s[nt][1] - m0v);
            const float p2 = __expf(s[nt][2] - m1v);
            const float p3 = __expf(s[nt][3] - m1v);
            rs0 += p0 + p1;
            rs1 += p2 + p3;
            uint2 w0; w0.x = f2tf(p0); w0.y = f2tf(p1);
            uint2 w1; w1.x = f2tf(p2); w1.y = f2tf(p3);
            *(uint2*)&Pw[gid * PIT + nt * 8 + 2 * tig]       = w0;
            *(uint2*)&Pw[(gid + 8) * PIT + nt * 8 + 2 * tig] = w1;
        }
        rs0 += __shfl_xor_sync(0xffffffffu, rs0, 1);
        rs0 += __shfl_xor_sync(0xffffffffu, rs0, 2);
        rs1 += __shfl_xor_sync(0xffffffffu, rs1, 1);
        rs1 += __shfl_xor_sync(0xffffffffu, rs1, 2);
        l0 = l0 * al0 + rs0;
        l1 = l1 * al1 + rs1;

        #pragma unroll
        for (int nt = 0; nt < 8; nt++) {
            o[nt][0] *= al0; o[nt][1] *= al0;
            o[nt][2] *= al1; o[nt][3] *= al1;
        }

        __syncwarp();

        #pragma unroll
        for (int kc = 0; kc < 8; kc++) {
            unsigned af[4];
            af[0] = Pw[gid * PIT + kc * 8 + tig];
            af[1] = Pw[(gid + 8) * PIT + kc * 8 + tig];
            af[2] = Pw[gid * PIT + kc * 8 + tig + 4];
            af[3] = Pw[(gid + 8) * PIT + kc * 8 + tig + 4];
            #pragma unroll
            for (int nt = 0; nt < 8; nt++) {
                unsigned bfv[2];
                const unsigned* p = &Vs[(kc * 8 + tig) * PIT + nt * 8 + gid];
                bfv[0] = p[0];
                bfv[1] = p[4 * PIT];
                mma_tf32(o[nt], af, bfv);
            }
        }
    }

    const float il0 = 1.0f / l0;
    const float il1 = 1.0f / l1;
    float* ob = g_ctx + (size_t)(b * SEQ + q0 + warp * 16) * DMODEL + h * 64;
    #pragma unroll
    for (int nt = 0; nt < 8; nt++) {
        const int col = nt * 8 + 2 * tig;
        *(float2*)&ob[gid * DMODEL + col] =
            make_float2(o[nt][0] * il0, o[nt][1] * il0);
        *(float2*)&ob[(gid + 8) * DMODEL + col] =
            make_float2(o[nt][2] * il1, o[nt][3] * il1);
    }
}

// ---------------------------------------------------------------------------
extern "C" void kernel_launch(void* const* d_in, const int* in_sizes, int n_in,
                              void* d_out, int out_size)
{
    const float* x  = (const float*)d_in[0];
    const float* Wq = (const float*)d_in[1];
    const float* Wk = (const float*)d_in[2];
    const float* Wv = (const float*)d_in[3];
    const float* Wo = (const float*)d_in[4];
    float* out = (float*)d_out;

    float* q_p;   cudaGetSymbolAddress((void**)&q_p,   g_q);
    float* k_p;   cudaGetSymbolAddress((void**)&k_p,   g_k);
    float* v_p;   cudaGetSymbolAddress((void**)&v_p,   g_v);
    float* ctx_p; cudaGetSymbolAddress((void**)&ctx_p, g_ctx);

    cudaFuncSetAttribute(attn_mma_kernel,
                         cudaFuncAttributeMaxDynamicSharedMemorySize,
                         ATTN_SMEM_BYTES);

    rope_table_kernel<<<256, 256>>>();

    // Fused QKV projections (z selects Wq/Wk/Wv).
    dim3 gq(DMODEL / BN, NQ / BM, 3);
    gemm_kernel<0><<<gq, 256>>>(x, Wq, Wk, Wv, q_p, k_p, v_p);

    dim3 ga(SEQ / 64, NHEADS, BATCH);
    attn_mma_kernel<<<ga, 128, ATTN_SMEM_BYTES>>>();

    dim3 go(DMODEL / BN, NQ / BM, 1);
    gemm_kernel<1><<<go, 256>>>(ctx_p, Wo, 0, 0, out, 0, 0);
}

// round 8
// speedup vs baseline: 1.2307x; 1.1378x over previous
#include <cuda_runtime.h>
#include <cuda_fp16.h>
#include <stdint.h>
#include <math.h>

#define BATCH   2
#define SEQ     2048
#define DMODEL  1024
#define NHEADS  16
#define DK      64
#define NQ      (BATCH * SEQ)   // 4096 rows
#define GK      DMODEL          // GEMM K dim (all 4 projections)

// Scratch (allocation-free: device globals)
__device__ float g_q[BATCH * NHEADS * SEQ * DK];   // [b][h][s][d]
__device__ float g_k[BATCH * NHEADS * SEQ * DK];
__device__ float g_v[BATCH * NHEADS * SEQ * DK];
__device__ float g_ctx[NQ * DMODEL];               // [b*S+s][h*64+d]
__device__ float g_cos[SEQ * 32];                  // rope table [s][d/2]
__device__ float g_sin[SEQ * 32];

// ---------------------------------------------------------------------------
// RoPE table
// ---------------------------------------------------------------------------
__global__ void rope_table_kernel()
{
    int i = blockIdx.x * 256 + threadIdx.x;   // SEQ*32 = 65536
    int s = i >> 5;
    int j = i & 31;
    float freq = powf(10000.0f, -(float)(2 * j) * (1.0f / 64.0f));
    float sn, cs;
    sincosf((float)s * freq, &sn, &cs);
    g_cos[i] = cs;
    g_sin[i] = sn;
}

// ---------------------------------------------------------------------------
// Helpers
// ---------------------------------------------------------------------------
__device__ __forceinline__ unsigned f2tf(float f)
{
    unsigned u;
    asm("cvt.rna.tf32.f32 %0, %1;" : "=r"(u) : "f"(f));
    return u;
}

__device__ __forceinline__ unsigned f2h2(float x, float y)
{
    __half2 h = __float22half2_rn(make_float2(x, y));
    return *(unsigned*)&h;
}

__device__ __forceinline__ void mma_tf32(float* d, const unsigned* a, const unsigned* b)
{
    asm volatile(
        "mma.sync.aligned.m16n8k8.row.col.f32.tf32.tf32.f32 "
        "{%0,%1,%2,%3},{%4,%5,%6,%7},{%8,%9},{%0,%1,%2,%3};"
        : "+f"(d[0]), "+f"(d[1]), "+f"(d[2]), "+f"(d[3])
        : "r"(a[0]), "r"(a[1]), "r"(a[2]), "r"(a[3]), "r"(b[0]), "r"(b[1]));
}

__device__ __forceinline__ void mma_f16(float* d, const unsigned* a, const unsigned* b)
{
    asm volatile(
        "mma.sync.aligned.m16n8k16.row.col.f32.f16.f16.f32 "
        "{%0,%1,%2,%3},{%4,%5,%6,%7},{%8,%9},{%0,%1,%2,%3};"
        : "+f"(d[0]), "+f"(d[1]), "+f"(d[2]), "+f"(d[3])
        : "r"(a[0]), "r"(a[1]), "r"(a[2]), "r"(a[3]), "r"(b[0]), "r"(b[1]));
}

// ---------------------------------------------------------------------------
// fp16 tensor-core GEMM: C[M,N] = A[M,K] @ W[N,K]^T  (fp32 accumulate)
// CTA tile 128x128, 8 warps (2m x 4n), warp tile 64x32.
// BK=16 halfs per stage (one m16n8k16 per frag pair), double-buffered.
// smem rows: 16 halfs = 8 uints, pitch LDP2=10 uints (pad vs conflicts).
//
// m16n8k16 fragment maps (half2 units, g=lane>>2, t=lane&3):
//   A: a0=[g][t] a1=[g+8][t] a2=[g][t+4] a3=[g+8][t+4]
//   B: b0=[n][t] b1=[n][t+4]       (B[k][n] = W[n][k], K-major in W rows)
//
// OUTMODE=0: fused QKV (z selects W/dst; z<2 RoPE scatter, z=2 plain scatter)
// OUTMODE=1: row-major store
// ---------------------------------------------------------------------------
#define BM   128
#define BN   128
#define BKH  16     // halfs per stage
#define LDP2 10     // smem row pitch in uints (8 data + 2 pad)

template <int OUTMODE>
__global__ __launch_bounds__(256) void gemm_kernel(
    const float* __restrict__ A,
    const float* __restrict__ W0,
    const float* __restrict__ W1,
    const float* __restrict__ W2,
    float* __restrict__ D0,
    float* __restrict__ D1,
    float* __restrict__ D2)
{
    __shared__ __align__(16) unsigned As[2][BM * LDP2];
    __shared__ __align__(16) unsigned Bs[2][BN * LDP2];

    const int z = blockIdx.z;
    const float* W = OUTMODE ? W0 : (z == 0 ? W0 : (z == 1 ? W1 : W2));
    float* dst     = OUTMODE ? D0 : (z == 0 ? D0 : (z == 1 ? D1 : D2));

    const int tid  = threadIdx.x;
    const int lane = tid & 31;
    const int warp = tid >> 5;
    const int wm   = warp & 1;    // 0..1
    const int wn   = warp >> 1;   // 0..3
    const int m0   = blockIdx.y * BM;
    const int n0   = blockIdx.x * BN;

    const int g = lane >> 2;      // 0..7
    const int t = lane & 3;       // 0..3

    // Staging: thread -> rows (row0, row0+64), float offset kc..kc+3 of 16.
    const int row0 = tid >> 2;           // 0..63
    const int kc   = (tid & 3) * 4;      // 0,4,8,12
    const int ku   = kc >> 1;            // uint (half2) offset: 0,2,4,6

    const float* Aptr = A + (size_t)(m0 + row0) * GK + kc;
    const float* Wptr = W + (size_t)(n0 + row0) * GK + kc;

    float c[4][4][4];
    #pragma unroll
    for (int i = 0; i < 4; i++)
        #pragma unroll
        for (int j = 0; j < 4; j++)
            #pragma unroll
            for (int r = 0; r < 4; r++)
                c[i][j][r] = 0.f;

    const int NST = GK / BKH;   // 64 stages

    float4 la0, la1, lb0, lb1;
    auto stage_store = [&](int buf) {
        uint2 u;
        u.x = f2h2(la0.x, la0.y); u.y = f2h2(la0.z, la0.w);
        *(uint2*)&As[buf][row0 * LDP2 + ku] = u;
        u.x = f2h2(la1.x, la1.y); u.y = f2h2(la1.z, la1.w);
        *(uint2*)&As[buf][(row0 + 64) * LDP2 + ku] = u;
        u.x = f2h2(lb0.x, lb0.y); u.y = f2h2(lb0.z, lb0.w);
        *(uint2*)&Bs[buf][row0 * LDP2 + ku] = u;
        u.x = f2h2(lb1.x, lb1.y); u.y = f2h2(lb1.z, lb1.w);
        *(uint2*)&Bs[buf][(row0 + 64) * LDP2 + ku] = u;
    };

    la0 = *(const float4*)Aptr;
    la1 = *(const float4*)(Aptr + (size_t)64 * GK);
    lb0 = *(const float4*)Wptr;
    lb1 = *(const float4*)(Wptr + (size_t)64 * GK);
    stage_store(0);
    __syncthreads();

    for (int s = 0; s < NST; s++) {
        const int cur = s & 1;
        if (s + 1 < NST) {
            const float* ap = Aptr + (s + 1) * BKH;
            const float* wp = Wptr + (s + 1) * BKH;
            la0 = *(const float4*)ap;
            la1 = *(const float4*)(ap + (size_t)64 * GK);
            lb0 = *(const float4*)wp;
            lb1 = *(const float4*)(wp + (size_t)64 * GK);
        }

        unsigned af[4][4], bf[4][2];
        #pragma unroll
        for (int mf = 0; mf < 4; mf++) {
            const int m = wm * 64 + mf * 16 + g;
            const unsigned* p = &As[cur][m * LDP2 + t];
            af[mf][0] = p[0];
            af[mf][1] = p[8 * LDP2];
            af[mf][2] = p[4];
            af[mf][3] = p[8 * LDP2 + 4];
        }
        #pragma unroll
        for (int nf = 0; nf < 4; nf++) {
            const int n = wn * 32 + nf * 8 + g;
            const unsigned* p = &Bs[cur][n * LDP2 + t];
            bf[nf][0] = p[0];
            bf[nf][1] = p[4];
        }
        #pragma unroll
        for (int mf = 0; mf < 4; mf++)
            #pragma unroll
            for (int nf = 0; nf < 4; nf++)
                mma_f16(c[mf][nf], af[mf], bf[nf]);

        if (s + 1 < NST) {
            stage_store(cur ^ 1);
            __syncthreads();
        }
    }

    // Epilogue (same C layout as m16n8k8: rows g,g+8; cols 2t,2t+1)
    #pragma unroll
    for (int mf = 0; mf < 4; mf++) {
        #pragma unroll
        for (int nf = 0; nf < 4; nf++) {
            const int col = n0 + wn * 32 + nf * 8 + t * 2;   // even
            #pragma unroll
            for (int half = 0; half < 2; half++) {
                const int r  = m0 + wm * 64 + mf * 16 + g + half * 8;
                const float x0 = c[mf][nf][half * 2 + 0];
                const float x1 = c[mf][nf][half * 2 + 1];
                if (OUTMODE) {
                    *(float2*)&dst[(size_t)r * DMODEL + col] = make_float2(x0, x1);
                } else {
                    const int bb = r >> 11;            // / SEQ
                    const int sI = r & (SEQ - 1);
                    const int h  = col >> 6;
                    const int dd = col & 63;           // even
                    const int base = ((bb * NHEADS + h) * SEQ + sI) * DK + dd;
                    if (z < 2) {
                        const float cs = g_cos[sI * 32 + (dd >> 1)];
                        const float sn = g_sin[sI * 32 + (dd >> 1)];
                        *(float2*)&dst[base] =
                            make_float2(x0 * cs - x1 * sn, x0 * sn + x1 * cs);
                    } else {
                        *(float2*)&dst[base] = make_float2(x0, x1);
                    }
                }
            }
        }
    }
}

// ---------------------------------------------------------------------------
// Kernel 2: tensor-core flash attention (tf32 mma.sync) — proven R3/R5 version.
// ---------------------------------------------------------------------------
#define PIT 68
#define ATTN_SMEM_BYTES ((64 * PIT * 2 + 4 * 16 * PIT) * 4)

__global__ __launch_bounds__(128) void attn_mma_kernel()
{
    extern __shared__ unsigned sm[];
    unsigned* Ks = sm;                     // [key][d]
    unsigned* Vs = sm + 64 * PIT;          // [key][d]
    unsigned* Pw = sm + 2 * 64 * PIT + (threadIdx.x >> 5) * 16 * PIT;

    const int tid  = threadIdx.x;
    const int lane = tid & 31;
    const int warp = tid >> 5;
    const int gid  = lane >> 2;   // 0..7
    const int tig  = lane & 3;    // 0..3

    const int h  = blockIdx.y;
    const int b  = blockIdx.z;
    const int qb = gridDim.x - 1 - blockIdx.x;   // heavy blocks first
    const int q0 = qb * 64;

    const float* kbase = g_k + (size_t)((b * NHEADS + h) * SEQ) * DK;
    const float* vbase = g_v + (size_t)((b * NHEADS + h) * SEQ) * DK;
    const float* qbase = g_q + (size_t)((b * NHEADS + h) * SEQ + q0) * DK;

    unsigned qf[8][4];
    {
        const int r0 = warp * 16 + gid;
        #pragma unroll
        for (int kc = 0; kc < 8; kc++) {
            qf[kc][0] = f2tf(0.125f * qbase[r0 * 64 + kc * 8 + tig]);
            qf[kc][1] = f2tf(0.125f * qbase[(r0 + 8) * 64 + kc * 8 + tig]);
            qf[kc][2] = f2tf(0.125f * qbase[r0 * 64 + kc * 8 + tig + 4]);
            qf[kc][3] = f2tf(0.125f * qbase[(r0 + 8) * 64 + kc * 8 + tig + 4]);
        }
    }

    float o[8][4];
    #pragma unroll
    for (int nt = 0; nt < 8; nt++)
        #pragma unroll
        for (int r = 0; r < 4; r++)
            o[nt][r] = 0.f;
    float m0v = -1e30f, m1v = -1e30f, l0 = 0.f, l1 = 0.f;

    const int ntiles = qb + 1;
    for (int kt = 0; kt < ntiles; kt++) {
        __syncthreads();
        #pragma unroll
        for (int i = 0; i < 8; i++) {
            const int idx = i * 128 + tid;
            const int key = idx >> 4;
            const int c4  = (idx & 15) * 4;
            float4 kv = *(const float4*)&kbase[(size_t)(kt * 64 + key) * 64 + c4];
            float4 vv = *(const float4*)&vbase[(size_t)(kt * 64 + key) * 64 + c4];
            uint4 u;
            u.x = f2tf(kv.x); u.y = f2tf(kv.y); u.z = f2tf(kv.z); u.w = f2tf(kv.w);
            *(uint4*)&Ks[key * PIT + c4] = u;
            u.x = f2tf(vv.x); u.y = f2tf(vv.y); u.z = f2tf(vv.z); u.w = f2tf(vv.w);
            *(uint4*)&Vs[key * PIT + c4] = u;
        }
        __syncthreads();

        float s[8][4];
        #pragma unroll
        for (int nt = 0; nt < 8; nt++) {
            s[nt][0] = s[nt][1] = s[nt][2] = s[nt][3] = 0.f;
            #pragma unroll
            for (int kc = 0; kc < 8; kc++) {
                unsigned bfv[2];
                const unsigned* p = &Ks[(nt * 8 + gid) * PIT + kc * 8 + tig];
                bfv[0] = p[0];
                bfv[1] = p[4];
                mma_tf32(s[nt], qf[kc], bfv);
            }
        }

        if (kt == qb) {
            const int r0 = warp * 16 + gid;
            #pragma unroll
            for (int nt = 0; nt < 8; nt++) {
                const int c = nt * 8 + 2 * tig;
                if (c > r0)         s[nt][0] = -1e30f;
                if (c + 1 > r0)     s[nt][1] = -1e30f;
                if (c > r0 + 8)     s[nt][2] = -1e30f;
                if (c + 1 > r0 + 8) s[nt][3] = -1e30f;
            }
        }

        float mx0 = -1e30f, mx1 = -1e30f;
        #pragma unroll
        for (int nt = 0; nt < 8; nt++) {
            mx0 = fmaxf(mx0, fmaxf(s[nt][0], s[nt][1]));
            mx1 = fmaxf(mx1, fmaxf(s[nt][2], s[nt][3]));
        }
        mx0 = fmaxf(mx0, __shfl_xor_sync(0xffffffffu, mx0, 1));
        mx0 = fmaxf(mx0, __shfl_xor_sync(0xffffffffu, mx0, 2));
        mx1 = fmaxf(mx1, __shfl_xor_sync(0xffffffffu, mx1, 1));
        mx1 = fmaxf(mx1, __shfl_xor_sync(0xffffffffu, mx1, 2));

        const float nm0 = fmaxf(m0v, mx0);
        const float nm1 = fmaxf(m1v, mx1);
        const float al0 = __expf(m0v - nm0);
        const float al1 = __expf(m1v - nm1);
        m0v = nm0; m1v = nm1;

        float rs0 = 0.f, rs1 = 0.f;
        #pragma unroll
        for (int nt = 0; nt < 8; nt++) {
            const float p0 = __expf(s[nt][0] - m0v);
            const float p1 = __expf(s[nt][1] - m0v);
            const float p2 = __expf(s[nt][2] - m1v);
            const float p3 = __expf(s[nt][3] - m1v);
            rs0 += p0 + p1;
            rs1 += p2 + p3;
            uint2 w0; w0.x = f2tf(p0); w0.y = f2tf(p1);
            uint2 w1; w1.x = f2tf(p2); w1.y = f2tf(p3);
            *(uint2*)&Pw[gid * PIT + nt * 8 + 2 * tig]       = w0;
            *(uint2*)&Pw[(gid + 8) * PIT + nt * 8 + 2 * tig] = w1;
        }
        rs0 += __shfl_xor_sync(0xffffffffu, rs0, 1);
        rs0 += __shfl_xor_sync(0xffffffffu, rs0, 2);
        rs1 += __shfl_xor_sync(0xffffffffu, rs1, 1);
        rs1 += __shfl_xor_sync(0xffffffffu, rs1, 2);
        l0 = l0 * al0 + rs0;
        l1 = l1 * al1 + rs1;

        #pragma unroll
        for (int nt = 0; nt < 8; nt++) {
            o[nt][0] *= al0; o[nt][1] *= al0;
            o[nt][2] *= al1; o[nt][3] *= al1;
        }

        __syncwarp();

        #pragma unroll
        for (int kc = 0; kc < 8; kc++) {
            unsigned af[4];
            af[0] = Pw[gid * PIT + kc * 8 + tig];
            af[1] = Pw[(gid + 8) * PIT + kc * 8 + tig];
            af[2] = Pw[gid * PIT + kc * 8 + tig + 4];
            af[3] = Pw[(gid + 8) * PIT + kc * 8 + tig + 4];
            #pragma unroll
            for (int nt = 0; nt < 8; nt++) {
                unsigned bfv[2];
                const unsigned* p = &Vs[(kc * 8 + tig) * PIT + nt * 8 + gid];
                bfv[0] = p[0];
                bfv[1] = p[4 * PIT];
                mma_tf32(o[nt], af, bfv);
            }
        }
    }

    const float il0 = 1.0f / l0;
    const float il1 = 1.0f / l1;
    float* ob = g_ctx + (size_t)(b * SEQ + q0 + warp * 16) * DMODEL + h * 64;
    #pragma unroll
    for (int nt = 0; nt < 8; nt++) {
        const int col = nt * 8 + 2 * tig;
        *(float2*)&ob[gid * DMODEL + col] =
            make_float2(o[nt][0] * il0, o[nt][1] * il0);
        *(float2*)&ob[(gid + 8) * DMODEL + col] =
            make_float2(o[nt][2] * il1, o[nt][3] * il1);
    }
}

// ---------------------------------------------------------------------------
extern "C" void kernel_launch(void* const* d_in, const int* in_sizes, int n_in,
                              void* d_out, int out_size)
{
    const float* x  = (const float*)d_in[0];
    const float* Wq = (const float*)d_in[1];
    const float* Wk = (const float*)d_in[2];
    const float* Wv = (const float*)d_in[3];
    const float* Wo = (const float*)d_in[4];
    float* out = (float*)d_out;

    float* q_p;   cudaGetSymbolAddress((void**)&q_p,   g_q);
    float* k_p;   cudaGetSymbolAddress((void**)&k_p,   g_k);
    float* v_p;   cudaGetSymbolAddress((void**)&v_p,   g_v);
    float* ctx_p; cudaGetSymbolAddress((void**)&ctx_p, g_ctx);

    cudaFuncSetAttribute(attn_mma_kernel,
                         cudaFuncAttributeMaxDynamicSharedMemorySize,
                         ATTN_SMEM_BYTES);

    rope_table_kernel<<<256, 256>>>();

    // Fused QKV projections (z selects Wq/Wk/Wv).
    dim3 gq(DMODEL / BN, NQ / BM, 3);
    gemm_kernel<0><<<gq, 256>>>(x, Wq, Wk, Wv, q_p, k_p, v_p);

    dim3 ga(SEQ / 64, NHEADS, BATCH);
    attn_mma_kernel<<<ga, 128, ATTN_SMEM_BYTES>>>();

    dim3 go(DMODEL / BN, NQ / BM, 1);
    gemm_kernel<1><<<go, 256>>>(ctx_p, Wo, 0, 0, out, 0, 0);
}

// round 9
// speedup vs baseline: 1.3327x; 1.0829x over previous
#include <cuda_runtime.h>
#include <cuda_fp16.h>
#include <stdint.h>
#include <math.h>

#define BATCH   2
#define SEQ     2048
#define DMODEL  1024
#define NHEADS  16
#define DK      64
#define NQ      (BATCH * SEQ)   // 4096 rows
#define GK      DMODEL          // GEMM K dim (all 4 projections)

// Scratch (allocation-free: device globals)
__device__ float g_q[BATCH * NHEADS * SEQ * DK];   // [b][h][s][d]
__device__ float g_k[BATCH * NHEADS * SEQ * DK];
__device__ float g_v[BATCH * NHEADS * SEQ * DK];
__device__ float g_ctx[NQ * DMODEL];               // [b*S+s][h*64+d]
__device__ float g_cos[SEQ * 32];                  // rope table [s][d/2]
__device__ float g_sin[SEQ * 32];

// ---------------------------------------------------------------------------
// RoPE table
// ---------------------------------------------------------------------------
__global__ void rope_table_kernel()
{
    int i = blockIdx.x * 256 + threadIdx.x;   // SEQ*32 = 65536
    int s = i >> 5;
    int j = i & 31;
    float freq = powf(10000.0f, -(float)(2 * j) * (1.0f / 64.0f));
    float sn, cs;
    sincosf((float)s * freq, &sn, &cs);
    g_cos[i] = cs;
    g_sin[i] = sn;
}

// ---------------------------------------------------------------------------
// Helpers
// ---------------------------------------------------------------------------
__device__ __forceinline__ unsigned f2h2(float x, float y)
{
    __half2 h = __float22half2_rn(make_float2(x, y));
    return *(unsigned*)&h;
}

__device__ __forceinline__ void mma_f16(float* d, const unsigned* a, const unsigned* b)
{
    asm volatile(
        "mma.sync.aligned.m16n8k16.row.col.f32.f16.f16.f32 "
        "{%0,%1,%2,%3},{%4,%5,%6,%7},{%8,%9},{%0,%1,%2,%3};"
        : "+f"(d[0]), "+f"(d[1]), "+f"(d[2]), "+f"(d[3])
        : "r"(a[0]), "r"(a[1]), "r"(a[2]), "r"(a[3]), "r"(b[0]), "r"(b[1]));
}

// ---------------------------------------------------------------------------
// fp16 tensor-core GEMM: C[M,N] = A[M,K] @ W[N,K]^T  (fp32 accumulate)
// CTA tile 128x128, 8 warps (2m x 4n), warp tile 64x32.
// BK=16 halfs per stage, double-buffered, smem pitch 10 uints.
// OUTMODE=0: fused QKV (z selects W/dst; z<2 RoPE scatter, z=2 plain scatter)
// OUTMODE=1: row-major store
// ---------------------------------------------------------------------------
#define BM   128
#define BN   128
#define BKH  16     // halfs per stage
#define LDP2 10     // smem row pitch in uints (8 data + 2 pad)

template <int OUTMODE>
__global__ __launch_bounds__(256) void gemm_kernel(
    const float* __restrict__ A,
    const float* __restrict__ W0,
    const float* __restrict__ W1,
    const float* __restrict__ W2,
    float* __restrict__ D0,
    float* __restrict__ D1,
    float* __restrict__ D2)
{
    __shared__ __align__(16) unsigned As[2][BM * LDP2];
    __shared__ __align__(16) unsigned Bs[2][BN * LDP2];

    const int z = blockIdx.z;
    const float* W = OUTMODE ? W0 : (z == 0 ? W0 : (z == 1 ? W1 : W2));
    float* dst     = OUTMODE ? D0 : (z == 0 ? D0 : (z == 1 ? D1 : D2));

    const int tid  = threadIdx.x;
    const int lane = tid & 31;
    const int warp = tid >> 5;
    const int wm   = warp & 1;    // 0..1
    const int wn   = warp >> 1;   // 0..3
    const int m0   = blockIdx.y * BM;
    const int n0   = blockIdx.x * BN;

    const int g = lane >> 2;      // 0..7
    const int t = lane & 3;       // 0..3

    const int row0 = tid >> 2;           // 0..63
    const int kc   = (tid & 3) * 4;      // 0,4,8,12
    const int ku   = kc >> 1;            // 0,2,4,6

    const float* Aptr = A + (size_t)(m0 + row0) * GK + kc;
    const float* Wptr = W + (size_t)(n0 + row0) * GK + kc;

    float c[4][4][4];
    #pragma unroll
    for (int i = 0; i < 4; i++)
        #pragma unroll
        for (int j = 0; j < 4; j++)
            #pragma unroll
            for (int r = 0; r < 4; r++)
                c[i][j][r] = 0.f;

    const int NST = GK / BKH;   // 64 stages

    float4 la0, la1, lb0, lb1;
    auto stage_store = [&](int buf) {
        uint2 u;
        u.x = f2h2(la0.x, la0.y); u.y = f2h2(la0.z, la0.w);
        *(uint2*)&As[buf][row0 * LDP2 + ku] = u;
        u.x = f2h2(la1.x, la1.y); u.y = f2h2(la1.z, la1.w);
        *(uint2*)&As[buf][(row0 + 64) * LDP2 + ku] = u;
        u.x = f2h2(lb0.x, lb0.y); u.y = f2h2(lb0.z, lb0.w);
        *(uint2*)&Bs[buf][row0 * LDP2 + ku] = u;
        u.x = f2h2(lb1.x, lb1.y); u.y = f2h2(lb1.z, lb1.w);
        *(uint2*)&Bs[buf][(row0 + 64) * LDP2 + ku] = u;
    };

    la0 = *(const float4*)Aptr;
    la1 = *(const float4*)(Aptr + (size_t)64 * GK);
    lb0 = *(const float4*)Wptr;
    lb1 = *(const float4*)(Wptr + (size_t)64 * GK);
    stage_store(0);
    __syncthreads();

    for (int s = 0; s < NST; s++) {
        const int cur = s & 1;
        if (s + 1 < NST) {
            const float* ap = Aptr + (s + 1) * BKH;
            const float* wp = Wptr + (s + 1) * BKH;
            la0 = *(const float4*)ap;
            la1 = *(const float4*)(ap + (size_t)64 * GK);
            lb0 = *(const float4*)wp;
            lb1 = *(const float4*)(wp + (size_t)64 * GK);
        }

        unsigned af[4][4], bf[4][2];
        #pragma unroll
        for (int mf = 0; mf < 4; mf++) {
            const int m = wm * 64 + mf * 16 + g;
            const unsigned* p = &As[cur][m * LDP2 + t];
            af[mf][0] = p[0];
            af[mf][1] = p[8 * LDP2];
            af[mf][2] = p[4];
            af[mf][3] = p[8 * LDP2 + 4];
        }
        #pragma unroll
        for (int nf = 0; nf < 4; nf++) {
            const int n = wn * 32 + nf * 8 + g;
            const unsigned* p = &Bs[cur][n * LDP2 + t];
            bf[nf][0] = p[0];
            bf[nf][1] = p[4];
        }
        #pragma unroll
        for (int mf = 0; mf < 4; mf++)
            #pragma unroll
            for (int nf = 0; nf < 4; nf++)
                mma_f16(c[mf][nf], af[mf], bf[nf]);

        if (s + 1 < NST) {
            stage_store(cur ^ 1);
            __syncthreads();
        }
    }

    // Epilogue (C layout: rows g,g+8; cols 2t,2t+1)
    #pragma unroll
    for (int mf = 0; mf < 4; mf++) {
        #pragma unroll
        for (int nf = 0; nf < 4; nf++) {
            const int col = n0 + wn * 32 + nf * 8 + t * 2;   // even
            #pragma unroll
            for (int half = 0; half < 2; half++) {
                const int r  = m0 + wm * 64 + mf * 16 + g + half * 8;
                const float x0 = c[mf][nf][half * 2 + 0];
                const float x1 = c[mf][nf][half * 2 + 1];
                if (OUTMODE) {
                    *(float2*)&dst[(size_t)r * DMODEL + col] = make_float2(x0, x1);
                } else {
                    const int bb = r >> 11;            // / SEQ
                    const int sI = r & (SEQ - 1);
                    const int h  = col >> 6;
                    const int dd = col & 63;           // even
                    const int base = ((bb * NHEADS + h) * SEQ + sI) * DK + dd;
                    if (z < 2) {
                        const float cs = g_cos[sI * 32 + (dd >> 1)];
                        const float sn = g_sin[sI * 32 + (dd >> 1)];
                        *(float2*)&dst[base] =
                            make_float2(x0 * cs - x1 * sn, x0 * sn + x1 * cs);
                    } else {
                        *(float2*)&dst[base] = make_float2(x0, x1);
                    }
                }
            }
        }
    }
}

// ---------------------------------------------------------------------------
// Kernel 2: fp16 tensor-core flash attention (m16n8k16, fp32 accumulate).
// CTA: 4 warps, 64 queries (16 per warp). Key tiles of 64.
// Smem (all half2-as-uint, pitch 36 uints = 4 mod 32 -> conflict-free):
//   Ks: [key][d]   64 rows x 32 uints   (QK B-operand)
//   Vt: [d][key]   64 rows x 32 uints   (PV B-operand, V transposed)
//   Pw: per-warp [qrow][key] 16 x 32    (PV A-operand)
// ---------------------------------------------------------------------------
#define APIT 36
#define ATTN_SMEM_BYTES ((64 * APIT * 2 + 4 * 16 * APIT) * 4)

__global__ __launch_bounds__(128) void attn_mma_kernel()
{
    extern __shared__ unsigned sm[];
    unsigned* Ks = sm;                       // [key][d half2]
    unsigned* Vt = sm + 64 * APIT;           // [d][key half2]
    unsigned* Pw = sm + 2 * 64 * APIT + (threadIdx.x >> 5) * 16 * APIT;

    const int tid  = threadIdx.x;
    const int lane = tid & 31;
    const int warp = tid >> 5;
    const int gid  = lane >> 2;   // 0..7
    const int tig  = lane & 3;    // 0..3

    const int h  = blockIdx.y;
    const int b  = blockIdx.z;
    const int qb = gridDim.x - 1 - blockIdx.x;   // heavy blocks first
    const int q0 = qb * 64;

    const float* kbase = g_k + (size_t)((b * NHEADS + h) * SEQ) * DK;
    const float* vbase = g_v + (size_t)((b * NHEADS + h) * SEQ) * DK;
    const float* qbase = g_q + (size_t)((b * NHEADS + h) * SEQ + q0) * DK;

    // Q fragments fp16 (scaled by 1/8). A-frag m16k16: rows r0,r0+8;
    // half2 idx t -> k=2t,2t+1; +4 -> k=2t+8,2t+9; chunk kc covers k=kc*16..
    unsigned qf[4][4];
    {
        const int r0 = warp * 16 + gid;
        #pragma unroll
        for (int kc = 0; kc < 4; kc++) {
            const int k0 = kc * 16 + 2 * tig;
            qf[kc][0] = f2h2(0.125f * qbase[r0 * 64 + k0],
                             0.125f * qbase[r0 * 64 + k0 + 1]);
            qf[kc][1] = f2h2(0.125f * qbase[(r0 + 8) * 64 + k0],
                             0.125f * qbase[(r0 + 8) * 64 + k0 + 1]);
            qf[kc][2] = f2h2(0.125f * qbase[r0 * 64 + k0 + 8],
                             0.125f * qbase[r0 * 64 + k0 + 9]);
            qf[kc][3] = f2h2(0.125f * qbase[(r0 + 8) * 64 + k0 + 8],
                             0.125f * qbase[(r0 + 8) * 64 + k0 + 9]);
        }
    }

    float o[8][4];
    #pragma unroll
    for (int nt = 0; nt < 8; nt++)
        #pragma unroll
        for (int r = 0; r < 4; r++)
            o[nt][r] = 0.f;
    float m0v = -1e30f, m1v = -1e30f, l0 = 0.f, l1 = 0.f;

    const int ntiles = qb + 1;
    for (int kt = 0; kt < ntiles; kt++) {
        __syncthreads();   // previous-tile smem reads complete
        // Stage K -> Ks [key][d], V -> Vt [d][key] (transposed, half scalar)
        #pragma unroll
        for (int i = 0; i < 8; i++) {
            const int idx = i * 128 + tid;
            const int key = idx >> 4;
            const int c4  = (idx & 15) * 4;
            float4 kv = *(const float4*)&kbase[(size_t)(kt * 64 + key) * 64 + c4];
            float4 vv = *(const float4*)&vbase[(size_t)(kt * 64 + key) * 64 + c4];
            uint2 u;
            u.x = f2h2(kv.x, kv.y); u.y = f2h2(kv.z, kv.w);
            *(uint2*)&Ks[key * APIT + (idx & 15) * 2] = u;
            __half* vh = (__half*)Vt;
            vh[(c4 + 0) * (2 * APIT) + key] = __float2half_rn(vv.x);
            vh[(c4 + 1) * (2 * APIT) + key] = __float2half_rn(vv.y);
            vh[(c4 + 2) * (2 * APIT) + key] = __float2half_rn(vv.z);
            vh[(c4 + 3) * (2 * APIT) + key] = __float2half_rn(vv.w);
        }
        __syncthreads();

        // S = Q K^T (16 x 64 per warp): 8 nt x 4 kc mma
        float s[8][4];
        #pragma unroll
        for (int nt = 0; nt < 8; nt++) {
            s[nt][0] = s[nt][1] = s[nt][2] = s[nt][3] = 0.f;
            #pragma unroll
            for (int kc = 0; kc < 4; kc++) {
                unsigned bfv[2];
                const unsigned* p = &Ks[(nt * 8 + gid) * APIT + kc * 8 + tig];
                bfv[0] = p[0];
                bfv[1] = p[4];
                mma_f16(s[nt], qf[kc], bfv);
            }
        }

        // Causal mask on diagonal tile
        if (kt == qb) {
            const int r0 = warp * 16 + gid;
            #pragma unroll
            for (int nt = 0; nt < 8; nt++) {
                const int c = nt * 8 + 2 * tig;
                if (c > r0)         s[nt][0] = -1e30f;
                if (c + 1 > r0)     s[nt][1] = -1e30f;
                if (c > r0 + 8)     s[nt][2] = -1e30f;
                if (c + 1 > r0 + 8) s[nt][3] = -1e30f;
            }
        }

        // Row max (rows gid and gid+8)
        float mx0 = -1e30f, mx1 = -1e30f;
        #pragma unroll
        for (int nt = 0; nt < 8; nt++) {
            mx0 = fmaxf(mx0, fmaxf(s[nt][0], s[nt][1]));
            mx1 = fmaxf(mx1, fmaxf(s[nt][2], s[nt][3]));
        }
        mx0 = fmaxf(mx0, __shfl_xor_sync(0xffffffffu, mx0, 1));
        mx0 = fmaxf(mx0, __shfl_xor_sync(0xffffffffu, mx0, 2));
        mx1 = fmaxf(mx1, __shfl_xor_sync(0xffffffffu, mx1, 1));
        mx1 = fmaxf(mx1, __shfl_xor_sync(0xffffffffu, mx1, 2));

        const float nm0 = fmaxf(m0v, mx0);
        const float nm1 = fmaxf(m1v, mx1);
        const float al0 = __expf(m0v - nm0);
        const float al1 = __expf(m1v - nm1);
        m0v = nm0; m1v = nm1;

        // p = exp(s - m) -> P smem as half2 (cols 2tig,2tig+1 adjacent)
        float rs0 = 0.f, rs1 = 0.f;
        #pragma unroll
        for (int nt = 0; nt < 8; nt++) {
            const float p0 = __expf(s[nt][0] - m0v);
            const float p1 = __expf(s[nt][1] - m0v);
            const float p2 = __expf(s[nt][2] - m1v);
            const float p3 = __expf(s[nt][3] - m1v);
            rs0 += p0 + p1;
            rs1 += p2 + p3;
            Pw[gid * APIT + nt * 4 + tig]       = f2h2(p0, p1);
            Pw[(gid + 8) * APIT + nt * 4 + tig] = f2h2(p2, p3);
        }
        rs0 += __shfl_xor_sync(0xffffffffu, rs0, 1);
        rs0 += __shfl_xor_sync(0xffffffffu, rs0, 2);
        rs1 += __shfl_xor_sync(0xffffffffu, rs1, 1);
        rs1 += __shfl_xor_sync(0xffffffffu, rs1, 2);
        l0 = l0 * al0 + rs0;
        l1 = l1 * al1 + rs1;

        // Rescale O
        #pragma unroll
        for (int nt = 0; nt < 8; nt++) {
            o[nt][0] *= al0; o[nt][1] *= al0;
            o[nt][2] *= al1; o[nt][3] *= al1;
        }

        __syncwarp();   // P visible across lanes

        // O += P @ V : A = P [16 x 64 keys], B = Vt [d][key]
        #pragma unroll
        for (int kc = 0; kc < 4; kc++) {
            unsigned af[4];
            af[0] = Pw[gid * APIT + kc * 8 + tig];
            af[1] = Pw[(gid + 8) * APIT + kc * 8 + tig];
            af[2] = Pw[gid * APIT + kc * 8 + tig + 4];
            af[3] = Pw[(gid + 8) * APIT + kc * 8 + tig + 4];
            #pragma unroll
            for (int nt = 0; nt < 8; nt++) {
                unsigned bfv[2];
                const unsigned* p = &Vt[(nt * 8 + gid) * APIT + kc * 8 + tig];
                bfv[0] = p[0];
                bfv[1] = p[4];
                mma_f16(o[nt], af, bfv);
            }
        }
    }

    // Epilogue: O /= l, scatter to ctx [b*S+q][h*64+d]
    const float il0 = 1.0f / l0;
    const float il1 = 1.0f / l1;
    float* ob = g_ctx + (size_t)(b * SEQ + q0 + warp * 16) * DMODEL + h * 64;
    #pragma unroll
    for (int nt = 0; nt < 8; nt++) {
        const int col = nt * 8 + 2 * tig;
        *(float2*)&ob[gid * DMODEL + col] =
            make_float2(o[nt][0] * il0, o[nt][1] * il0);
        *(float2*)&ob[(gid + 8) * DMODEL + col] =
            make_float2(o[nt][2] * il1, o[nt][3] * il1);
    }
}

// ---------------------------------------------------------------------------
extern "C" void kernel_launch(void* const* d_in, const int* in_sizes, int n_in,
                              void* d_out, int out_size)
{
    const float* x  = (const float*)d_in[0];
    const float* Wq = (const float*)d_in[1];
    const float* Wk = (const float*)d_in[2];
    const float* Wv = (const float*)d_in[3];
    const float* Wo = (const float*)d_in[4];
    float* out = (float*)d_out;

    float* q_p;   cudaGetSymbolAddress((void**)&q_p,   g_q);
    float* k_p;   cudaGetSymbolAddress((void**)&k_p,   g_k);
    float* v_p;   cudaGetSymbolAddress((void**)&v_p,   g_v);
    float* ctx_p; cudaGetSymbolAddress((void**)&ctx_p, g_ctx);

    cudaFuncSetAttribute(attn_mma_kernel,
                         cudaFuncAttributeMaxDynamicSharedMemorySize,
                         ATTN_SMEM_BYTES);

    rope_table_kernel<<<256, 256>>>();

    // Fused QKV projections (z selects Wq/Wk/Wv).
    dim3 gq(DMODEL / BN, NQ / BM, 3);
    gemm_kernel<0><<<gq, 256>>>(x, Wq, Wk, Wv, q_p, k_p, v_p);

    dim3 ga(SEQ / 64, NHEADS, BATCH);
    attn_mma_kernel<<<ga, 128, ATTN_SMEM_BYTES>>>();

    dim3 go(DMODEL / BN, NQ / BM, 1);
    gemm_kernel<1><<<go, 256>>>(ctx_p, Wo, 0, 0, out, 0, 0);
}

// round 10
// speedup vs baseline: 1.6164x; 1.2129x over previous
#include <cuda_runtime.h>
#include <cuda_fp16.h>
#include <stdint.h>
#include <math.h>

#define BATCH   2
#define SEQ     2048
#define DMODEL  1024
#define NHEADS  16
#define DK      64
#define NQ      (BATCH * SEQ)   // 4096 rows
#define GK      DMODEL

// fp16 scratch (allocation-free: device globals)
__device__ __half g_xh [NQ * DMODEL];
__device__ __half g_wq [DMODEL * DMODEL];
__device__ __half g_wk [DMODEL * DMODEL];
__device__ __half g_wv [DMODEL * DMODEL];
__device__ __half g_wo [DMODEL * DMODEL];
__device__ __half g_q  [BATCH * NHEADS * SEQ * DK];   // pre-scaled by 0.125
__device__ __half g_k  [BATCH * NHEADS * SEQ * DK];
__device__ __half g_v  [BATCH * NHEADS * SEQ * DK];
__device__ __half g_ctx[NQ * DMODEL];
__device__ float  g_cos[SEQ * 32];
__device__ float  g_sin[SEQ * 32];

// ---------------------------------------------------------------------------
__global__ void rope_table_kernel()
{
    int i = blockIdx.x * 256 + threadIdx.x;   // SEQ*32 = 65536
    int s = i >> 5;
    int j = i & 31;
    float freq = powf(10000.0f, -(float)(2 * j) * (1.0f / 64.0f));
    float sn, cs;
    sincosf((float)s * freq, &sn, &cs);
    g_cos[i] = cs;
    g_sin[i] = sn;
}

// ---------------------------------------------------------------------------
// Pre-convert: x + 4 weights -> fp16. float2 granular, 4,194,304 float2.
// ---------------------------------------------------------------------------
#define NX2 (NQ * DMODEL / 2)          // 2097152
#define NW2 (DMODEL * DMODEL / 2)      // 524288

__global__ __launch_bounds__(256) void convert_kernel(
    const float* __restrict__ x,  const float* __restrict__ wq,
    const float* __restrict__ wk, const float* __restrict__ wv,
    const float* __restrict__ wo)
{
    int i = blockIdx.x * 256 + threadIdx.x;
    const float2* s;
    __half2* d;
    int j;
    if (i < NX2)                { s = (const float2*)x;  d = (__half2*)g_xh; j = i; }
    else if (i < NX2 + NW2)     { s = (const float2*)wq; d = (__half2*)g_wq; j = i - NX2; }
    else if (i < NX2 + 2 * NW2) { s = (const float2*)wk; d = (__half2*)g_wk; j = i - NX2 - NW2; }
    else if (i < NX2 + 3 * NW2) { s = (const float2*)wv; d = (__half2*)g_wv; j = i - NX2 - 2 * NW2; }
    else                        { s = (const float2*)wo; d = (__half2*)g_wo; j = i - NX2 - 3 * NW2; }
    d[j] = __float22half2_rn(s[j]);
}

// ---------------------------------------------------------------------------
// Helpers
// ---------------------------------------------------------------------------
__device__ __forceinline__ unsigned f2h2(float x, float y)
{
    __half2 h = __float22half2_rn(make_float2(x, y));
    return *(unsigned*)&h;
}

__device__ __forceinline__ void mma_f16(float* d, const unsigned* a, const unsigned* b)
{
    asm volatile(
        "mma.sync.aligned.m16n8k16.row.col.f32.f16.f16.f32 "
        "{%0,%1,%2,%3},{%4,%5,%6,%7},{%8,%9},{%0,%1,%2,%3};"
        : "+f"(d[0]), "+f"(d[1]), "+f"(d[2]), "+f"(d[3])
        : "r"(a[0]), "r"(a[1]), "r"(a[2]), "r"(a[3]), "r"(b[0]), "r"(b[1]));
}

__device__ __forceinline__ uint32_t smem_u32(const void* p)
{
    uint32_t a;
    asm("{ .reg .u64 t; cvta.to.shared.u64 t, %1; cvt.u32.u64 %0, t; }"
        : "=r"(a) : "l"(p));
    return a;
}

__device__ __forceinline__ void cp16(uint32_t saddr, const void* g)
{
    asm volatile("cp.async.cg.shared.global [%0], [%1], 16;"
                 :: "r"(saddr), "l"(g) : "memory");
}
#define CP_COMMIT() asm volatile("cp.async.commit_group;" ::: "memory")
#define CP_WAIT1()  asm volatile("cp.async.wait_group 1;" ::: "memory")

// ---------------------------------------------------------------------------
// fp16 cp.async GEMM: C[M,N] = A[M,K] @ W[N,K]^T (fp32 accumulate)
// CTA 128x128, 8 warps (2m x 4n), warp tile 64x32.
// BK=32 halfs/stage, 3-stage cp.async pipeline, smem pitch 20 uints/row.
// OUTMODE=0: fused QKV from g_xh (z: 0=q rope+0.125, 1=k rope, 2=v plain)
// OUTMODE=1: out = g_ctx @ g_wo^T, row-major fp32 store
// ---------------------------------------------------------------------------
#define BK2   32
#define NSTG  (GK / BK2)        // 32
#define RPIT  20                // uints per row (16 data + 4 pad)
#define TILEU (128 * RPIT)      // 2560 uints per tile
#define GEMM_SMEM (3 * 2 * TILEU * 4)   // 61440 B

template <int OUTMODE>
__global__ __launch_bounds__(256) void gemm_kernel(float* __restrict__ Dout)
{
    extern __shared__ unsigned Sg[];
    const uint32_t sb = smem_u32(Sg);

    const int z = blockIdx.z;
    const __half* Ah = OUTMODE ? g_ctx : g_xh;
    const __half* Wh = OUTMODE ? g_wo : (z == 0 ? g_wq : (z == 1 ? g_wk : g_wv));

    const int tid  = threadIdx.x;
    const int lane = tid & 31;
    const int warp = tid >> 5;
    const int wm   = warp & 1;
    const int wn   = warp >> 1;
    const int m0   = blockIdx.y * 128;
    const int n0   = blockIdx.x * 128;
    const int g    = lane >> 2;
    const int t    = lane & 3;

    // cp.async mapping: row = tid>>1 (0..127), chunks (tid&1)*2, +1 (16B each)
    const int row = tid >> 1;
    const int c0  = (tid & 1) * 2;
    const __half* ga = Ah + (size_t)(m0 + row) * GK + c0 * 8;
    const __half* gw = Wh + (size_t)(n0 + row) * GK + c0 * 8;
    const uint32_t da = sb + (row * RPIT + c0 * 4) * 4;

    auto issue = [&](int s, int p) {
        const uint32_t d0 = da + p * 2 * TILEU * 4;
        const __half* a = ga + s * BK2;
        const __half* w = gw + s * BK2;
        cp16(d0, a);
        cp16(d0 + 16, a + 8);
        cp16(d0 + TILEU * 4, w);
        cp16(d0 + TILEU * 4 + 16, w + 8);
    };

    float c[4][4][4];
    #pragma unroll
    for (int i = 0; i < 4; i++)
        #pragma unroll
        for (int j = 0; j < 4; j++)
            #pragma unroll
            for (int r = 0; r < 4; r++)
                c[i][j][r] = 0.f;

    issue(0, 0); CP_COMMIT();
    issue(1, 1); CP_COMMIT();

    for (int s = 0; s < NSTG; s++) {
        const int p = s % 3;
        CP_WAIT1();
        __syncthreads();
        if (s + 2 < NSTG) { issue(s + 2, (s + 2) % 3); CP_COMMIT(); }

        const unsigned base = p * 2 * TILEU;
        #pragma unroll
        for (int kc = 0; kc < 2; kc++) {
            unsigned af[4][4], bf[4][2];
            #pragma unroll
            for (int mf = 0; mf < 4; mf++) {
                const unsigned au = base + (wm * 64 + mf * 16 + g) * RPIT + kc * 8 + t;
                af[mf][0] = Sg[au];
                af[mf][1] = Sg[au + 8 * RPIT];
                af[mf][2] = Sg[au + 4];
                af[mf][3] = Sg[au + 8 * RPIT + 4];
            }
            #pragma unroll
            for (int nf = 0; nf < 4; nf++) {
                const unsigned bu = base + TILEU + (wn * 32 + nf * 8 + g) * RPIT + kc * 8 + t;
                bf[nf][0] = Sg[bu];
                bf[nf][1] = Sg[bu + 4];
            }
            #pragma unroll
            for (int mf = 0; mf < 4; mf++)
                #pragma unroll
                for (int nf = 0; nf < 4; nf++)
                    mma_f16(c[mf][nf], af[mf], bf[nf]);
        }
    }
    __syncthreads();

    // Epilogue (C layout: rows g,g+8; cols 2t,2t+1)
    __half* dsth = (OUTMODE == 0) ? (z == 0 ? g_q : (z == 1 ? g_k : g_v)) : 0;
    #pragma unroll
    for (int mf = 0; mf < 4; mf++) {
        #pragma unroll
        for (int nf = 0; nf < 4; nf++) {
            const int col = n0 + wn * 32 + nf * 8 + t * 2;   // even
            #pragma unroll
            for (int half = 0; half < 2; half++) {
                const int r  = m0 + wm * 64 + mf * 16 + g + half * 8;
                float x0 = c[mf][nf][half * 2 + 0];
                float x1 = c[mf][nf][half * 2 + 1];
                if (OUTMODE) {
                    *(float2*)&Dout[(size_t)r * DMODEL + col] = make_float2(x0, x1);
                } else {
                    const int bb = r >> 11;
                    const int sI = r & (SEQ - 1);
                    const int h  = col >> 6;
                    const int dd = col & 63;   // even
                    const int base = ((bb * NHEADS + h) * SEQ + sI) * DK + dd;
                    if (z < 2) {
                        const float cs = g_cos[sI * 32 + (dd >> 1)];
                        const float sn = g_sin[sI * 32 + (dd >> 1)];
                        float r0 = x0 * cs - x1 * sn;
                        float r1 = x0 * sn + x1 * cs;
                        if (z == 0) { r0 *= 0.125f; r1 *= 0.125f; }   // fold q scale
                        *(unsigned*)&dsth[base] = f2h2(r0, r1);
                    } else {
                        *(unsigned*)&dsth[base] = f2h2(x0, x1);
                    }
                }
            }
        }
    }
}

// ---------------------------------------------------------------------------
// fp16 tensor-core flash attention (m16n8k16, fp32 accumulate).
// CTA: 4 warps, 64 queries (16 per warp). Key tiles of 64.
// Inputs g_q (pre-scaled), g_k, g_v fp16; output g_ctx fp16.
// Smem (uint = half2, pitch 36 uints): Ks [key][d], Vt [d][key], Pw per-warp.
// ---------------------------------------------------------------------------
#define APIT 36
#define ATTN_SMEM_BYTES ((64 * APIT * 2 + 4 * 16 * APIT) * 4)

__global__ __launch_bounds__(128) void attn_mma_kernel()
{
    extern __shared__ unsigned sm[];
    unsigned* Ks = sm;                       // [key][d half2]
    unsigned* Vt = sm + 64 * APIT;           // [d][key half2]
    unsigned* Pw = sm + 2 * 64 * APIT + (threadIdx.x >> 5) * 16 * APIT;

    const int tid  = threadIdx.x;
    const int lane = tid & 31;
    const int warp = tid >> 5;
    const int gid  = lane >> 2;
    const int tig  = lane & 3;

    const int h  = blockIdx.y;
    const int b  = blockIdx.z;
    const int qb = gridDim.x - 1 - blockIdx.x;   // heavy blocks first
    const int q0 = qb * 64;

    const __half* kbase = g_k + (size_t)((b * NHEADS + h) * SEQ) * DK;
    const __half* vbase = g_v + (size_t)((b * NHEADS + h) * SEQ) * DK;

    // Q fragments: direct uint loads (half2-packed, pre-scaled by 0.125)
    unsigned qf[4][4];
    {
        const unsigned* qp =
            (const unsigned*)(g_q + (size_t)((b * NHEADS + h) * SEQ + q0) * DK);
        const int r0 = warp * 16 + gid;
        #pragma unroll
        for (int kc = 0; kc < 4; kc++) {
            qf[kc][0] = qp[r0 * 32 + kc * 8 + tig];
            qf[kc][1] = qp[(r0 + 8) * 32 + kc * 8 + tig];
            qf[kc][2] = qp[r0 * 32 + kc * 8 + tig + 4];
            qf[kc][3] = qp[(r0 + 8) * 32 + kc * 8 + tig + 4];
        }
    }

    float o[8][4];
    #pragma unroll
    for (int nt = 0; nt < 8; nt++)
        #pragma unroll
        for (int r = 0; r < 4; r++)
            o[nt][r] = 0.f;
    float m0v = -1e30f, m1v = -1e30f, l0 = 0.f, l1 = 0.f;

    const int ntiles = qb + 1;
    for (int kt = 0; kt < ntiles; kt++) {
        __syncthreads();
        // Stage: K -> Ks [key][d] (uint4 copies), V -> Vt [d][key] transposed.
        #pragma unroll
        for (int i = 0; i < 4; i++) {
            const int idx = i * 128 + tid;     // 512 chunks of 8 halfs
            const int key = idx >> 3;
            const int c8  = idx & 7;
            const __half* ksrc = kbase + (size_t)(kt * 64 + key) * 64 + c8 * 8;
            *(uint4*)&Ks[key * APIT + c8 * 4] = *(const uint4*)ksrc;
            uint4 vv = *(const uint4*)(vbase + (size_t)(kt * 64 + key) * 64 + c8 * 8);
            const __half* hh = (const __half*)&vv;
            __half* vh = (__half*)Vt;
            #pragma unroll
            for (int d8 = 0; d8 < 8; d8++)
                vh[(c8 * 8 + d8) * (2 * APIT) + key] = hh[d8];
        }
        __syncthreads();

        // S = Q K^T (16 x 64 per warp)
        float s[8][4];
        #pragma unroll
        for (int nt = 0; nt < 8; nt++) {
            s[nt][0] = s[nt][1] = s[nt][2] = s[nt][3] = 0.f;
            #pragma unroll
            for (int kc = 0; kc < 4; kc++) {
                unsigned bfv[2];
                const unsigned* p = &Ks[(nt * 8 + gid) * APIT + kc * 8 + tig];
                bfv[0] = p[0];
                bfv[1] = p[4];
                mma_f16(s[nt], qf[kc], bfv);
            }
        }

        // Causal mask on diagonal tile
        if (kt == qb) {
            const int r0 = warp * 16 + gid;
            #pragma unroll
            for (int nt = 0; nt < 8; nt++) {
                const int c = nt * 8 + 2 * tig;
                if (c > r0)         s[nt][0] = -1e30f;
                if (c + 1 > r0)     s[nt][1] = -1e30f;
                if (c > r0 + 8)     s[nt][2] = -1e30f;
                if (c + 1 > r0 + 8) s[nt][3] = -1e30f;
            }
        }

        float mx0 = -1e30f, mx1 = -1e30f;
        #pragma unroll
        for (int nt = 0; nt < 8; nt++) {
            mx0 = fmaxf(mx0, fmaxf(s[nt][0], s[nt][1]));
            mx1 = fmaxf(mx1, fmaxf(s[nt][2], s[nt][3]));
        }
        mx0 = fmaxf(mx0, __shfl_xor_sync(0xffffffffu, mx0, 1));
        mx0 = fmaxf(mx0, __shfl_xor_sync(0xffffffffu, mx0, 2));
        mx1 = fmaxf(mx1, __shfl_xor_sync(0xffffffffu, mx1, 1));
        mx1 = fmaxf(mx1, __shfl_xor_sync(0xffffffffu, mx1, 2));

        const float nm0 = fmaxf(m0v, mx0);
        const float nm1 = fmaxf(m1v, mx1);
        const float al0 = __expf(m0v - nm0);
        const float al1 = __expf(m1v - nm1);
        m0v = nm0; m1v = nm1;

        float rs0 = 0.f, rs1 = 0.f;
        #pragma unroll
        for (int nt = 0; nt < 8; nt++) {
            const float p0 = __expf(s[nt][0] - m0v);
            const float p1 = __expf(s[nt][1] - m0v);
            const float p2 = __expf(s[nt][2] - m1v);
            const float p3 = __expf(s[nt][3] - m1v);
            rs0 += p0 + p1;
            rs1 += p2 + p3;
            Pw[gid * APIT + nt * 4 + tig]       = f2h2(p0, p1);
            Pw[(gid + 8) * APIT + nt * 4 + tig] = f2h2(p2, p3);
        }
        rs0 += __shfl_xor_sync(0xffffffffu, rs0, 1);
        rs0 += __shfl_xor_sync(0xffffffffu, rs0, 2);
        rs1 += __shfl_xor_sync(0xffffffffu, rs1, 1);
        rs1 += __shfl_xor_sync(0xffffffffu, rs1, 2);
        l0 = l0 * al0 + rs0;
        l1 = l1 * al1 + rs1;

        #pragma unroll
        for (int nt = 0; nt < 8; nt++) {
            o[nt][0] *= al0; o[nt][1] *= al0;
            o[nt][2] *= al1; o[nt][3] *= al1;
        }

        __syncwarp();

        // O += P @ V
        #pragma unroll
        for (int kc = 0; kc < 4; kc++) {
            unsigned af[4];
            af[0] = Pw[gid * APIT + kc * 8 + tig];
            af[1] = Pw[(gid + 8) * APIT + kc * 8 + tig];
            af[2] = Pw[gid * APIT + kc * 8 + tig + 4];
            af[3] = Pw[(gid + 8) * APIT + kc * 8 + tig + 4];
            #pragma unroll
            for (int nt = 0; nt < 8; nt++) {
                unsigned bfv[2];
                const unsigned* p = &Vt[(nt * 8 + gid) * APIT + kc * 8 + tig];
                bfv[0] = p[0];
                bfv[1] = p[4];
                mma_f16(o[nt], af, bfv);
            }
        }
    }

    // Epilogue: O /= l, scatter fp16 to ctx [b*S+q][h*64+d]
    const float il0 = 1.0f / l0;
    const float il1 = 1.0f / l1;
    __half* ob = g_ctx + (size_t)(b * SEQ + q0 + warp * 16) * DMODEL + h * 64;
    #pragma unroll
    for (int nt = 0; nt < 8; nt++) {
        const int col = nt * 8 + 2 * tig;
        *(unsigned*)&ob[gid * DMODEL + col] =
            f2h2(o[nt][0] * il0, o[nt][1] * il0);
        *(unsigned*)&ob[(gid + 8) * DMODEL + col] =
            f2h2(o[nt][2] * il1, o[nt][3] * il1);
    }
}

// ---------------------------------------------------------------------------
extern "C" void kernel_launch(void* const* d_in, const int* in_sizes, int n_in,
                              void* d_out, int out_size)
{
    const float* x  = (const float*)d_in[0];
    const float* Wq = (const float*)d_in[1];
    const float* Wk = (const float*)d_in[2];
    const float* Wv = (const float*)d_in[3];
    const float* Wo = (const float*)d_in[4];
    float* out = (float*)d_out;

    cudaFuncSetAttribute(gemm_kernel<0>,
                         cudaFuncAttributeMaxDynamicSharedMemorySize, GEMM_SMEM);
    cudaFuncSetAttribute(gemm_kernel<1>,
                         cudaFuncAttributeMaxDynamicSharedMemorySize, GEMM_SMEM);
    cudaFuncSetAttribute(attn_mma_kernel,
                         cudaFuncAttributeMaxDynamicSharedMemorySize,
                         ATTN_SMEM_BYTES);

    rope_table_kernel<<<256, 256>>>();
    convert_kernel<<<(NX2 + 4 * NW2) / 256, 256>>>(x, Wq, Wk, Wv, Wo);

    dim3 gq(DMODEL / 128, NQ / 128, 3);
    gemm_kernel<0><<<gq, 256, GEMM_SMEM>>>(0);

    dim3 ga(SEQ / 64, NHEADS, BATCH);
    attn_mma_kernel<<<ga, 128, ATTN_SMEM_BYTES>>>();

    dim3 go(DMODEL / 128, NQ / 128, 1);
    gemm_kernel<1><<<go, 256, GEMM_SMEM>>>(out);
}

// round 11
// speedup vs baseline: 2.0715x; 1.2815x over previous
#include <cuda_runtime.h>
#include <cuda_fp16.h>
#include <stdint.h>
#include <math.h>

#define BATCH   2
#define SEQ     2048
#define DMODEL  1024
#define NHEADS  16
#define DK      64
#define NQ      (BATCH * SEQ)   // 4096 rows
#define GK      DMODEL

// fp16 scratch (allocation-free: device globals)
__device__ __half g_xh [NQ * DMODEL];
__device__ __half g_wq [DMODEL * DMODEL];
__device__ __half g_wk [DMODEL * DMODEL];
__device__ __half g_wv [DMODEL * DMODEL];
__device__ __half g_wo [DMODEL * DMODEL];
__device__ __half g_q  [BATCH * NHEADS * SEQ * DK];   // pre-scaled by 0.125
__device__ __half g_k  [BATCH * NHEADS * SEQ * DK];
__device__ __half g_v  [BATCH * NHEADS * SEQ * DK];
__device__ __half g_ctx[NQ * DMODEL];
__device__ float  g_cos[SEQ * 32];
__device__ float  g_sin[SEQ * 32];

// ---------------------------------------------------------------------------
__global__ void rope_table_kernel()
{
    int i = blockIdx.x * 256 + threadIdx.x;   // SEQ*32 = 65536
    int s = i >> 5;
    int j = i & 31;
    float freq = powf(10000.0f, -(float)(2 * j) * (1.0f / 64.0f));
    float sn, cs;
    sincosf((float)s * freq, &sn, &cs);
    g_cos[i] = cs;
    g_sin[i] = sn;
}

// ---------------------------------------------------------------------------
// Pre-convert: x + 4 weights -> fp16.
// ---------------------------------------------------------------------------
#define NX2 (NQ * DMODEL / 2)          // 2097152
#define NW2 (DMODEL * DMODEL / 2)      // 524288

__global__ __launch_bounds__(256) void convert_kernel(
    const float* __restrict__ x,  const float* __restrict__ wq,
    const float* __restrict__ wk, const float* __restrict__ wv,
    const float* __restrict__ wo)
{
    int i = blockIdx.x * 256 + threadIdx.x;
    const float2* s;
    __half2* d;
    int j;
    if (i < NX2)                { s = (const float2*)x;  d = (__half2*)g_xh; j = i; }
    else if (i < NX2 + NW2)     { s = (const float2*)wq; d = (__half2*)g_wq; j = i - NX2; }
    else if (i < NX2 + 2 * NW2) { s = (const float2*)wk; d = (__half2*)g_wk; j = i - NX2 - NW2; }
    else if (i < NX2 + 3 * NW2) { s = (const float2*)wv; d = (__half2*)g_wv; j = i - NX2 - 2 * NW2; }
    else                        { s = (const float2*)wo; d = (__half2*)g_wo; j = i - NX2 - 3 * NW2; }
    d[j] = __float22half2_rn(s[j]);
}

// ---------------------------------------------------------------------------
// Helpers
// ---------------------------------------------------------------------------
__device__ __forceinline__ unsigned f2h2(float x, float y)
{
    __half2 h = __float22half2_rn(make_float2(x, y));
    return *(unsigned*)&h;
}

__device__ __forceinline__ void mma_f16(float* d, const unsigned* a, const unsigned* b)
{
    asm volatile(
        "mma.sync.aligned.m16n8k16.row.col.f32.f16.f16.f32 "
        "{%0,%1,%2,%3},{%4,%5,%6,%7},{%8,%9},{%0,%1,%2,%3};"
        : "+f"(d[0]), "+f"(d[1]), "+f"(d[2]), "+f"(d[3])
        : "r"(a[0]), "r"(a[1]), "r"(a[2]), "r"(a[3]), "r"(b[0]), "r"(b[1]));
}

__device__ __forceinline__ uint32_t smem_u32(const void* p)
{
    uint32_t a;
    asm("{ .reg .u64 t; cvta.to.shared.u64 t, %1; cvt.u32.u64 %0, t; }"
        : "=r"(a) : "l"(p));
    return a;
}

__device__ __forceinline__ void cp16(uint32_t saddr, const void* g)
{
    asm volatile("cp.async.cg.shared.global [%0], [%1], 16;"
                 :: "r"(saddr), "l"(g) : "memory");
}
#define CP_COMMIT() asm volatile("cp.async.commit_group;" ::: "memory")
#define CP_WAIT1()  asm volatile("cp.async.wait_group 1;" ::: "memory")
#define CP_WAIT0()  asm volatile("cp.async.wait_group 0;" ::: "memory")

__device__ __forceinline__ void ldsm4(unsigned* r, uint32_t a)
{
    asm volatile("ldmatrix.sync.aligned.m8n8.x4.shared.b16 {%0,%1,%2,%3}, [%4];"
                 : "=r"(r[0]), "=r"(r[1]), "=r"(r[2]), "=r"(r[3]) : "r"(a));
}
__device__ __forceinline__ void ldsm4t(unsigned* r, uint32_t a)
{
    asm volatile("ldmatrix.sync.aligned.m8n8.x4.trans.shared.b16 {%0,%1,%2,%3}, [%4];"
                 : "=r"(r[0]), "=r"(r[1]), "=r"(r[2]), "=r"(r[3]) : "r"(a));
}

// ---------------------------------------------------------------------------
// fp16 cp.async GEMM (unchanged from R10-best)
// ---------------------------------------------------------------------------
#define BK2   32
#define NSTG  (GK / BK2)        // 32
#define RPIT  20
#define TILEU (128 * RPIT)
#define GEMM_SMEM (3 * 2 * TILEU * 4)

template <int OUTMODE>
__global__ __launch_bounds__(256) void gemm_kernel(float* __restrict__ Dout)
{
    extern __shared__ unsigned Sg[];
    const uint32_t sb = smem_u32(Sg);

    const int z = blockIdx.z;
    const __half* Ah = OUTMODE ? g_ctx : g_xh;
    const __half* Wh = OUTMODE ? g_wo : (z == 0 ? g_wq : (z == 1 ? g_wk : g_wv));

    const int tid  = threadIdx.x;
    const int lane = tid & 31;
    const int warp = tid >> 5;
    const int wm   = warp & 1;
    const int wn   = warp >> 1;
    const int m0   = blockIdx.y * 128;
    const int n0   = blockIdx.x * 128;
    const int g    = lane >> 2;
    const int t    = lane & 3;

    const int row = tid >> 1;
    const int c0  = (tid & 1) * 2;
    const __half* ga = Ah + (size_t)(m0 + row) * GK + c0 * 8;
    const __half* gw = Wh + (size_t)(n0 + row) * GK + c0 * 8;
    const uint32_t da = sb + (row * RPIT + c0 * 4) * 4;

    auto issue = [&](int s, int p) {
        const uint32_t d0 = da + p * 2 * TILEU * 4;
        const __half* a = ga + s * BK2;
        const __half* w = gw + s * BK2;
        cp16(d0, a);
        cp16(d0 + 16, a + 8);
        cp16(d0 + TILEU * 4, w);
        cp16(d0 + TILEU * 4 + 16, w + 8);
    };

    float c[4][4][4];
    #pragma unroll
    for (int i = 0; i < 4; i++)
        #pragma unroll
        for (int j = 0; j < 4; j++)
            #pragma unroll
            for (int r = 0; r < 4; r++)
                c[i][j][r] = 0.f;

    issue(0, 0); CP_COMMIT();
    issue(1, 1); CP_COMMIT();

    for (int s = 0; s < NSTG; s++) {
        const int p = s % 3;
        CP_WAIT1();
        __syncthreads();
        if (s + 2 < NSTG) { issue(s + 2, (s + 2) % 3); CP_COMMIT(); }

        const unsigned base = p * 2 * TILEU;
        #pragma unroll
        for (int kc = 0; kc < 2; kc++) {
            unsigned af[4][4], bf[4][2];
            #pragma unroll
            for (int mf = 0; mf < 4; mf++) {
                const unsigned au = base + (wm * 64 + mf * 16 + g) * RPIT + kc * 8 + t;
                af[mf][0] = Sg[au];
                af[mf][1] = Sg[au + 8 * RPIT];
                af[mf][2] = Sg[au + 4];
                af[mf][3] = Sg[au + 8 * RPIT + 4];
            }
            #pragma unroll
            for (int nf = 0; nf < 4; nf++) {
                const unsigned bu = base + TILEU + (wn * 32 + nf * 8 + g) * RPIT + kc * 8 + t;
                bf[nf][0] = Sg[bu];
                bf[nf][1] = Sg[bu + 4];
            }
            #pragma unroll
            for (int mf = 0; mf < 4; mf++)
                #pragma unroll
                for (int nf = 0; nf < 4; nf++)
                    mma_f16(c[mf][nf], af[mf], bf[nf]);
        }
    }
    __syncthreads();

    __half* dsth = (OUTMODE == 0) ? (z == 0 ? g_q : (z == 1 ? g_k : g_v)) : 0;
    #pragma unroll
    for (int mf = 0; mf < 4; mf++) {
        #pragma unroll
        for (int nf = 0; nf < 4; nf++) {
            const int col = n0 + wn * 32 + nf * 8 + t * 2;
            #pragma unroll
            for (int half = 0; half < 2; half++) {
                const int r  = m0 + wm * 64 + mf * 16 + g + half * 8;
                float x0 = c[mf][nf][half * 2 + 0];
                float x1 = c[mf][nf][half * 2 + 1];
                if (OUTMODE) {
                    *(float2*)&Dout[(size_t)r * DMODEL + col] = make_float2(x0, x1);
                } else {
                    const int bb = r >> 11;
                    const int sI = r & (SEQ - 1);
                    const int h  = col >> 6;
                    const int dd = col & 63;
                    const int base = ((bb * NHEADS + h) * SEQ + sI) * DK + dd;
                    if (z < 2) {
                        const float cs = g_cos[sI * 32 + (dd >> 1)];
                        const float sn = g_sin[sI * 32 + (dd >> 1)];
                        float r0 = x0 * cs - x1 * sn;
                        float r1 = x0 * sn + x1 * cs;
                        if (z == 0) { r0 *= 0.125f; r1 *= 0.125f; }
                        *(unsigned*)&dsth[base] = f2h2(r0, r1);
                    } else {
                        *(unsigned*)&dsth[base] = f2h2(x0, x1);
                    }
                }
            }
        }
    }
}

// ---------------------------------------------------------------------------
// fp16 flash attention: cp.async double-buffered K/V + ldmatrix fragments.
// CTA: 4 warps, 64 queries. Key tiles of 64.
// Smem (uints): Ks[2][64*APIT] | Vs[2][64*APIT] | Pw[4][16*APIT]  = 46080 B
// K and V both stored [key][d] (uint4-equivalent cp.async); QK B-frags via
// ldmatrix.x4, PV B-frags via ldmatrix.x4.trans. Pitch 36 -> conflict-free.
// ---------------------------------------------------------------------------
#define APIT  36
#define KVBUF (64 * APIT)   // 2304 uints
#define ATTN_SMEM_BYTES ((4 * KVBUF + 4 * 16 * APIT) * 4)   // 46080

__global__ __launch_bounds__(128) void attn_mma_kernel()
{
    extern __shared__ unsigned sm[];
    const uint32_t sb = smem_u32(sm);
    unsigned* Pw = sm + 4 * KVBUF + (threadIdx.x >> 5) * 16 * APIT;

    const int tid  = threadIdx.x;
    const int lane = tid & 31;
    const int warp = tid >> 5;
    const int gid  = lane >> 2;
    const int tig  = lane & 3;
    const int mat  = lane >> 3;   // ldmatrix matrix id
    const int mj   = lane & 7;    // ldmatrix row within matrix

    const int h  = blockIdx.y;
    const int b  = blockIdx.z;
    const int qb = gridDim.x - 1 - blockIdx.x;   // heavy blocks first
    const int q0 = qb * 64;

    const __half* kbase = g_k + (size_t)((b * NHEADS + h) * SEQ) * DK;
    const __half* vbase = g_v + (size_t)((b * NHEADS + h) * SEQ) * DK;

    // cp.async staging: 512 chunks of 16B per tile for each of K, V.
    auto stage = [&](int kt, int buf) {
        #pragma unroll
        for (int i = 0; i < 4; i++) {
            const int idx = i * 128 + tid;
            const int key = idx >> 3;
            const int c8  = idx & 7;
            const uint32_t doff = (key * APIT + c8 * 4) * 4;
            cp16(sb + buf * KVBUF * 4 + doff,
                 kbase + (size_t)(kt * 64 + key) * 64 + c8 * 8);
            cp16(sb + (2 + buf) * KVBUF * 4 + doff,
                 vbase + (size_t)(kt * 64 + key) * 64 + c8 * 8);
        }
    };

    // Q fragments: direct uint loads (half2-packed, pre-scaled by 0.125)
    unsigned qf[4][4];
    {
        const unsigned* qp =
            (const unsigned*)(g_q + (size_t)((b * NHEADS + h) * SEQ + q0) * DK);
        const int r0 = warp * 16 + gid;
        #pragma unroll
        for (int kc = 0; kc < 4; kc++) {
            qf[kc][0] = qp[r0 * 32 + kc * 8 + tig];
            qf[kc][1] = qp[(r0 + 8) * 32 + kc * 8 + tig];
            qf[kc][2] = qp[r0 * 32 + kc * 8 + tig + 4];
            qf[kc][3] = qp[(r0 + 8) * 32 + kc * 8 + tig + 4];
        }
    }

    float o[8][4];
    #pragma unroll
    for (int nt = 0; nt < 8; nt++)
        #pragma unroll
        for (int r = 0; r < 4; r++)
            o[nt][r] = 0.f;
    float m0v = -1e30f, m1v = -1e30f, l0 = 0.f, l1 = 0.f;

    const int ntiles = qb + 1;
    stage(0, 0); CP_COMMIT();

    for (int kt = 0; kt < ntiles; kt++) {
        const int cur = kt & 1;
        if (kt + 1 < ntiles) { stage(kt + 1, cur ^ 1); CP_COMMIT(); CP_WAIT1(); }
        else                 { CP_WAIT0(); }
        __syncthreads();

        // S = Q K^T. B-frags: ldmatrix.x4 on Ks[key][d].
        // mat0/1: keys ntp*16+mj / +8... (mat>>1 selects key-octet pair),
        // mat&1 selects d+8 half -> r[0],r[1] = b for nt=2ntp; r[2],r[3] = nt=2ntp+1
        float s[8][4];
        #pragma unroll
        for (int nt = 0; nt < 8; nt++)
            s[nt][0] = s[nt][1] = s[nt][2] = s[nt][3] = 0.f;
        #pragma unroll
        for (int kc = 0; kc < 4; kc++) {
            #pragma unroll
            for (int ntp = 0; ntp < 4; ntp++) {
                const uint32_t a = sb +
                    (cur * KVBUF + (ntp * 16 + (mat >> 1) * 8 + mj) * APIT +
                     kc * 8 + (mat & 1) * 4) * 4;
                unsigned r[4];
                ldsm4(r, a);
                mma_f16(s[2 * ntp],     qf[kc], r);
                mma_f16(s[2 * ntp + 1], qf[kc], r + 2);
            }
        }

        // Causal mask on diagonal tile
        if (kt == qb) {
            const int r0 = warp * 16 + gid;
            #pragma unroll
            for (int nt = 0; nt < 8; nt++) {
                const int c = nt * 8 + 2 * tig;
                if (c > r0)         s[nt][0] = -1e30f;
                if (c + 1 > r0)     s[nt][1] = -1e30f;
                if (c > r0 + 8)     s[nt][2] = -1e30f;
                if (c + 1 > r0 + 8) s[nt][3] = -1e30f;
            }
        }

        float mx0 = -1e30f, mx1 = -1e30f;
        #pragma unroll
        for (int nt = 0; nt < 8; nt++) {
            mx0 = fmaxf(mx0, fmaxf(s[nt][0], s[nt][1]));
            mx1 = fmaxf(mx1, fmaxf(s[nt][2], s[nt][3]));
        }
        mx0 = fmaxf(mx0, __shfl_xor_sync(0xffffffffu, mx0, 1));
        mx0 = fmaxf(mx0, __shfl_xor_sync(0xffffffffu, mx0, 2));
        mx1 = fmaxf(mx1, __shfl_xor_sync(0xffffffffu, mx1, 1));
        mx1 = fmaxf(mx1, __shfl_xor_sync(0xffffffffu, mx1, 2));

        const float nm0 = fmaxf(m0v, mx0);
        const float nm1 = fmaxf(m1v, mx1);
        const float al0 = __expf(m0v - nm0);
        const float al1 = __expf(m1v - nm1);
        m0v = nm0; m1v = nm1;

        float rs0 = 0.f, rs1 = 0.f;
        #pragma unroll
        for (int nt = 0; nt < 8; nt++) {
            const float p0 = __expf(s[nt][0] - m0v);
            const float p1 = __expf(s[nt][1] - m0v);
            const float p2 = __expf(s[nt][2] - m1v);
            const float p3 = __expf(s[nt][3] - m1v);
            rs0 += p0 + p1;
            rs1 += p2 + p3;
            Pw[gid * APIT + nt * 4 + tig]       = f2h2(p0, p1);
            Pw[(gid + 8) * APIT + nt * 4 + tig] = f2h2(p2, p3);
        }
        rs0 += __shfl_xor_sync(0xffffffffu, rs0, 1);
        rs0 += __shfl_xor_sync(0xffffffffu, rs0, 2);
        rs1 += __shfl_xor_sync(0xffffffffu, rs1, 1);
        rs1 += __shfl_xor_sync(0xffffffffu, rs1, 2);
        l0 = l0 * al0 + rs0;
        l1 = l1 * al1 + rs1;

        #pragma unroll
        for (int nt = 0; nt < 8; nt++) {
            o[nt][0] *= al0; o[nt][1] *= al0;
            o[nt][2] *= al1; o[nt][3] *= al1;
        }

        __syncwarp();   // P visible across lanes

        // O += P @ V. B-frags: ldmatrix.x4.trans on Vs[key][d].
        // mat&1 selects key-octet (b0/b1), mat>>1 selects d+8 (nt pair).
        #pragma unroll
        for (int kcv = 0; kcv < 4; kcv++) {
            unsigned af[4];
            af[0] = Pw[gid * APIT + kcv * 8 + tig];
            af[1] = Pw[(gid + 8) * APIT + kcv * 8 + tig];
            af[2] = Pw[gid * APIT + kcv * 8 + tig + 4];
            af[3] = Pw[(gid + 8) * APIT + kcv * 8 + tig + 4];
            #pragma unroll
            for (int ntp = 0; ntp < 4; ntp++) {
                const uint32_t a = sb +
                    ((2 + cur) * KVBUF + (kcv * 16 + (mat & 1) * 8 + mj) * APIT +
                     ntp * 8 + (mat >> 1) * 4) * 4;
                unsigned r[4];
                ldsm4t(r, a);
                mma_f16(o[2 * ntp],     af, r);
                mma_f16(o[2 * ntp + 1], af, r + 2);
            }
        }
        __syncthreads();
    }

    // Epilogue: O /= l, scatter fp16 to ctx
    const float il0 = 1.0f / l0;
    const float il1 = 1.0f / l1;
    __half* ob = g_ctx + (size_t)(b * SEQ + q0 + warp * 16) * DMODEL + h * 64;
    #pragma unroll
    for (int nt = 0; nt < 8; nt++) {
        const int col = nt * 8 + 2 * tig;
        *(unsigned*)&ob[gid * DMODEL + col] =
            f2h2(o[nt][0] * il0, o[nt][1] * il0);
        *(unsigned*)&ob[(gid + 8) * DMODEL + col] =
            f2h2(o[nt][2] * il1, o[nt][3] * il1);
    }
}

// ---------------------------------------------------------------------------
extern "C" void kernel_launch(void* const* d_in, const int* in_sizes, int n_in,
                              void* d_out, int out_size)
{
    const float* x  = (const float*)d_in[0];
    const float* Wq = (const float*)d_in[1];
    const float* Wk = (const float*)d_in[2];
    const float* Wv = (const float*)d_in[3];
    const float* Wo = (const float*)d_in[4];
    float* out = (float*)d_out;

    cudaFuncSetAttribute(gemm_kernel<0>,
                         cudaFuncAttributeMaxDynamicSharedMemorySize, GEMM_SMEM);
    cudaFuncSetAttribute(gemm_kernel<1>,
                         cudaFuncAttributeMaxDynamicSharedMemorySize, GEMM_SMEM);
    cudaFuncSetAttribute(attn_mma_kernel,
                         cudaFuncAttributeMaxDynamicSharedMemorySize,
                         ATTN_SMEM_BYTES);

    rope_table_kernel<<<256, 256>>>();
    convert_kernel<<<(NX2 + 4 * NW2) / 256, 256>>>(x, Wq, Wk, Wv, Wo);

    dim3 gq(DMODEL / 128, NQ / 128, 3);
    gemm_kernel<0><<<gq, 256, GEMM_SMEM>>>(0);

    dim3 ga(SEQ / 64, NHEADS, BATCH);
    attn_mma_kernel<<<ga, 128, ATTN_SMEM_BYTES>>>();

    dim3 go(DMODEL / 128, NQ / 128, 1);
    gemm_kernel<1><<<go, 256, GEMM_SMEM>>>(out);
}

// round 12
// speedup vs baseline: 2.2111x; 1.0674x over previous
#include <cuda_runtime.h>
#include <cuda_fp16.h>
#include <stdint.h>
#include <math.h>

#define BATCH   2
#define SEQ     2048
#define DMODEL  1024
#define NHEADS  16
#define DK      64
#define NQ      (BATCH * SEQ)   // 4096 rows
#define GK      DMODEL

// fp16 scratch (allocation-free: device globals)
__device__ __half g_xh [NQ * DMODEL];
__device__ __half g_wq [DMODEL * DMODEL];
__device__ __half g_wk [DMODEL * DMODEL];
__device__ __half g_wv [DMODEL * DMODEL];
__device__ __half g_wo [DMODEL * DMODEL];
__device__ __half g_q  [BATCH * NHEADS * SEQ * DK];   // pre-scaled by 0.125
__device__ __half g_k  [BATCH * NHEADS * SEQ * DK];
__device__ __half g_v  [BATCH * NHEADS * SEQ * DK];
__device__ __half g_ctx[NQ * DMODEL];
__device__ float  g_cos[SEQ * 32];
__device__ float  g_sin[SEQ * 32];

// ---------------------------------------------------------------------------
__global__ void rope_table_kernel()
{
    int i = blockIdx.x * 256 + threadIdx.x;   // SEQ*32 = 65536
    int s = i >> 5;
    int j = i & 31;
    float freq = powf(10000.0f, -(float)(2 * j) * (1.0f / 64.0f));
    float sn, cs;
    sincosf((float)s * freq, &sn, &cs);
    g_cos[i] = cs;
    g_sin[i] = sn;
}

// ---------------------------------------------------------------------------
// Pre-convert: x + 4 weights -> fp16.
// ---------------------------------------------------------------------------
#define NX2 (NQ * DMODEL / 2)          // 2097152
#define NW2 (DMODEL * DMODEL / 2)      // 524288

__global__ __launch_bounds__(256) void convert_kernel(
    const float* __restrict__ x,  const float* __restrict__ wq,
    const float* __restrict__ wk, const float* __restrict__ wv,
    const float* __restrict__ wo)
{
    int i = blockIdx.x * 256 + threadIdx.x;
    const float2* s;
    __half2* d;
    int j;
    if (i < NX2)                { s = (const float2*)x;  d = (__half2*)g_xh; j = i; }
    else if (i < NX2 + NW2)     { s = (const float2*)wq; d = (__half2*)g_wq; j = i - NX2; }
    else if (i < NX2 + 2 * NW2) { s = (const float2*)wk; d = (__half2*)g_wk; j = i - NX2 - NW2; }
    else if (i < NX2 + 3 * NW2) { s = (const float2*)wv; d = (__half2*)g_wv; j = i - NX2 - 2 * NW2; }
    else                        { s = (const float2*)wo; d = (__half2*)g_wo; j = i - NX2 - 3 * NW2; }
    d[j] = __float22half2_rn(s[j]);
}

// ---------------------------------------------------------------------------
// Helpers
// ---------------------------------------------------------------------------
__device__ __forceinline__ unsigned f2h2(float x, float y)
{
    __half2 h = __float22half2_rn(make_float2(x, y));
    return *(unsigned*)&h;
}

__device__ __forceinline__ void mma_f16(float* d, const unsigned* a, const unsigned* b)
{
    asm volatile(
        "mma.sync.aligned.m16n8k16.row.col.f32.f16.f16.f32 "
        "{%0,%1,%2,%3},{%4,%5,%6,%7},{%8,%9},{%0,%1,%2,%3};"
        : "+f"(d[0]), "+f"(d[1]), "+f"(d[2]), "+f"(d[3])
        : "r"(a[0]), "r"(a[1]), "r"(a[2]), "r"(a[3]), "r"(b[0]), "r"(b[1]));
}

__device__ __forceinline__ uint32_t smem_u32(const void* p)
{
    uint32_t a;
    asm("{ .reg .u64 t; cvta.to.shared.u64 t, %1; cvt.u32.u64 %0, t; }"
        : "=r"(a) : "l"(p));
    return a;
}

__device__ __forceinline__ void cp16(uint32_t saddr, const void* g)
{
    asm volatile("cp.async.cg.shared.global [%0], [%1], 16;"
                 :: "r"(saddr), "l"(g) : "memory");
}
#define CP_COMMIT() asm volatile("cp.async.commit_group;" ::: "memory")
#define CP_WAIT1()  asm volatile("cp.async.wait_group 1;" ::: "memory")
#define CP_WAIT0()  asm volatile("cp.async.wait_group 0;" ::: "memory")

__device__ __forceinline__ void ldsm4(unsigned* r, uint32_t a)
{
    asm volatile("ldmatrix.sync.aligned.m8n8.x4.shared.b16 {%0,%1,%2,%3}, [%4];"
                 : "=r"(r[0]), "=r"(r[1]), "=r"(r[2]), "=r"(r[3]) : "r"(a));
}
__device__ __forceinline__ void ldsm4t(unsigned* r, uint32_t a)
{
    asm volatile("ldmatrix.sync.aligned.m8n8.x4.trans.shared.b16 {%0,%1,%2,%3}, [%4];"
                 : "=r"(r[0]), "=r"(r[1]), "=r"(r[2]), "=r"(r[3]) : "r"(a));
}

// ---------------------------------------------------------------------------
// fp16 cp.async GEMM; mainloop fragments via ldmatrix (this round).
// CTA 128x128, 8 warps (2m x 4n), warp tile 64x32, BK=32, 3-stage pipeline.
// A-frag ldsm map: mat&1 -> row-octet (+8), mat>>1 -> k-half (+4u); r = a0..a3.
// B-frag ldsm map: mat>>1 -> n-octet (+8), mat&1 -> k-half; r01/r23 -> nf pair.
// ---------------------------------------------------------------------------
#define BK2   32
#define NSTG  (GK / BK2)        // 32
#define RPIT  20
#define TILEU (128 * RPIT)
#define GEMM_SMEM (3 * 2 * TILEU * 4)

template <int OUTMODE>
__global__ __launch_bounds__(256) void gemm_kernel(float* __restrict__ Dout)
{
    extern __shared__ unsigned Sg[];
    const uint32_t sb = smem_u32(Sg);

    const int z = blockIdx.z;
    const __half* Ah = OUTMODE ? g_ctx : g_xh;
    const __half* Wh = OUTMODE ? g_wo : (z == 0 ? g_wq : (z == 1 ? g_wk : g_wv));

    const int tid  = threadIdx.x;
    const int lane = tid & 31;
    const int warp = tid >> 5;
    const int wm   = warp & 1;
    const int wn   = warp >> 1;
    const int m0   = blockIdx.y * 128;
    const int n0   = blockIdx.x * 128;
    const int g    = lane >> 2;
    const int t    = lane & 3;
    const int mat  = lane >> 3;
    const int mj   = lane & 7;

    const int row = tid >> 1;
    const int c0  = (tid & 1) * 2;
    const __half* ga = Ah + (size_t)(m0 + row) * GK + c0 * 8;
    const __half* gw = Wh + (size_t)(n0 + row) * GK + c0 * 8;
    const uint32_t da = sb + (row * RPIT + c0 * 4) * 4;

    auto issue = [&](int s, int p) {
        const uint32_t d0 = da + p * 2 * TILEU * 4;
        const __half* a = ga + s * BK2;
        const __half* w = gw + s * BK2;
        cp16(d0, a);
        cp16(d0 + 16, a + 8);
        cp16(d0 + TILEU * 4, w);
        cp16(d0 + TILEU * 4 + 16, w + 8);
    };

    float c[4][4][4];
    #pragma unroll
    for (int i = 0; i < 4; i++)
        #pragma unroll
        for (int j = 0; j < 4; j++)
            #pragma unroll
            for (int r = 0; r < 4; r++)
                c[i][j][r] = 0.f;

    issue(0, 0); CP_COMMIT();
    issue(1, 1); CP_COMMIT();

    for (int s = 0; s < NSTG; s++) {
        const int p = s % 3;
        CP_WAIT1();
        __syncthreads();
        if (s + 2 < NSTG) { issue(s + 2, (s + 2) % 3); CP_COMMIT(); }

        const unsigned base = p * 2 * TILEU;
        #pragma unroll
        for (int kc = 0; kc < 2; kc++) {
            unsigned af[4][4], bf[4][2];
            #pragma unroll
            for (int mf = 0; mf < 4; mf++) {
                const uint32_t a = sb + (base +
                    (wm * 64 + mf * 16 + (mat & 1) * 8 + mj) * RPIT +
                    kc * 8 + (mat >> 1) * 4) * 4;
                ldsm4(af[mf], a);
            }
            #pragma unroll
            for (int ntp = 0; ntp < 2; ntp++) {
                unsigned r[4];
                const uint32_t a = sb + (base + TILEU +
                    (wn * 32 + ntp * 16 + (mat >> 1) * 8 + mj) * RPIT +
                    kc * 8 + (mat & 1) * 4) * 4;
                ldsm4(r, a);
                bf[2 * ntp][0]     = r[0]; bf[2 * ntp][1]     = r[1];
                bf[2 * ntp + 1][0] = r[2]; bf[2 * ntp + 1][1] = r[3];
            }
            #pragma unroll
            for (int mf = 0; mf < 4; mf++)
                #pragma unroll
                for (int nf = 0; nf < 4; nf++)
                    mma_f16(c[mf][nf], af[mf], bf[nf]);
        }
    }
    __syncthreads();

    __half* dsth = (OUTMODE == 0) ? (z == 0 ? g_q : (z == 1 ? g_k : g_v)) : 0;
    #pragma unroll
    for (int mf = 0; mf < 4; mf++) {
        #pragma unroll
        for (int nf = 0; nf < 4; nf++) {
            const int col = n0 + wn * 32 + nf * 8 + t * 2;
            #pragma unroll
            for (int half = 0; half < 2; half++) {
                const int r  = m0 + wm * 64 + mf * 16 + g + half * 8;
                float x0 = c[mf][nf][half * 2 + 0];
                float x1 = c[mf][nf][half * 2 + 1];
                if (OUTMODE) {
                    *(float2*)&Dout[(size_t)r * DMODEL + col] = make_float2(x0, x1);
                } else {
                    const int bb = r >> 11;
                    const int sI = r & (SEQ - 1);
                    const int h  = col >> 6;
                    const int dd = col & 63;
                    const int base = ((bb * NHEADS + h) * SEQ + sI) * DK + dd;
                    if (z < 2) {
                        const float cs = g_cos[sI * 32 + (dd >> 1)];
                        const float sn = g_sin[sI * 32 + (dd >> 1)];
                        float r0 = x0 * cs - x1 * sn;
                        float r1 = x0 * sn + x1 * cs;
                        if (z == 0) { r0 *= 0.125f; r1 *= 0.125f; }
                        *(unsigned*)&dsth[base] = f2h2(r0, r1);
                    } else {
                        *(unsigned*)&dsth[base] = f2h2(x0, x1);
                    }
                }
            }
        }
    }
}

// ---------------------------------------------------------------------------
// fp16 flash attention: cp.async double-buffered K/V + ldmatrix fragments.
// __launch_bounds__(128, 4): cap regs at 128 -> 4 CTAs/SM (was 3, reg-capped).
// ---------------------------------------------------------------------------
#define APIT  36
#define KVBUF (64 * APIT)   // 2304 uints
#define ATTN_SMEM_BYTES ((4 * KVBUF + 4 * 16 * APIT) * 4)   // 46080

__global__ __launch_bounds__(128, 4) void attn_mma_kernel()
{
    extern __shared__ unsigned sm[];
    const uint32_t sb = smem_u32(sm);
    const int warp = threadIdx.x >> 5;
    const uint32_t pwoff = 4 * KVBUF + warp * 16 * APIT;   // uints
    unsigned* Pw = sm + pwoff;

    const int tid  = threadIdx.x;
    const int lane = tid & 31;
    const int gid  = lane >> 2;
    const int tig  = lane & 3;
    const int mat  = lane >> 3;
    const int mj   = lane & 7;

    const int h  = blockIdx.y;
    const int b  = blockIdx.z;
    const int qb = gridDim.x - 1 - blockIdx.x;   // heavy blocks first
    const int q0 = qb * 64;

    const __half* kbase = g_k + (size_t)((b * NHEADS + h) * SEQ) * DK;
    const __half* vbase = g_v + (size_t)((b * NHEADS + h) * SEQ) * DK;

    auto stage = [&](int kt, int buf) {
        #pragma unroll
        for (int i = 0; i < 4; i++) {
            const int idx = i * 128 + tid;
            const int key = idx >> 3;
            const int c8  = idx & 7;
            const uint32_t doff = (key * APIT + c8 * 4) * 4;
            cp16(sb + buf * KVBUF * 4 + doff,
                 kbase + (size_t)(kt * 64 + key) * 64 + c8 * 8);
            cp16(sb + (2 + buf) * KVBUF * 4 + doff,
                 vbase + (size_t)(kt * 64 + key) * 64 + c8 * 8);
        }
    };

    // Q fragments: direct uint loads (half2-packed, pre-scaled by 0.125)
    unsigned qf[4][4];
    {
        const unsigned* qp =
            (const unsigned*)(g_q + (size_t)((b * NHEADS + h) * SEQ + q0) * DK);
        const int r0 = warp * 16 + gid;
        #pragma unroll
        for (int kc = 0; kc < 4; kc++) {
            qf[kc][0] = qp[r0 * 32 + kc * 8 + tig];
            qf[kc][1] = qp[(r0 + 8) * 32 + kc * 8 + tig];
            qf[kc][2] = qp[r0 * 32 + kc * 8 + tig + 4];
            qf[kc][3] = qp[(r0 + 8) * 32 + kc * 8 + tig + 4];
        }
    }

    float o[8][4];
    #pragma unroll
    for (int nt = 0; nt < 8; nt++)
        #pragma unroll
        for (int r = 0; r < 4; r++)
            o[nt][r] = 0.f;
    float m0v = -1e30f, m1v = -1e30f, l0 = 0.f, l1 = 0.f;

    const int ntiles = qb + 1;
    stage(0, 0); CP_COMMIT();

    for (int kt = 0; kt < ntiles; kt++) {
        const int cur = kt & 1;
        if (kt + 1 < ntiles) { stage(kt + 1, cur ^ 1); CP_COMMIT(); CP_WAIT1(); }
        else                 { CP_WAIT0(); }
        __syncthreads();

        // S = Q K^T. B-frags via ldsm4 on Ks[key][d].
        float s[8][4];
        #pragma unroll
        for (int nt = 0; nt < 8; nt++)
            s[nt][0] = s[nt][1] = s[nt][2] = s[nt][3] = 0.f;
        #pragma unroll
        for (int kc = 0; kc < 4; kc++) {
            #pragma unroll
            for (int ntp = 0; ntp < 4; ntp++) {
                const uint32_t a = sb +
                    (cur * KVBUF + (ntp * 16 + (mat >> 1) * 8 + mj) * APIT +
                     kc * 8 + (mat & 1) * 4) * 4;
                unsigned r[4];
                ldsm4(r, a);
                mma_f16(s[2 * ntp],     qf[kc], r);
                mma_f16(s[2 * ntp + 1], qf[kc], r + 2);
            }
        }

        // Causal mask on diagonal tile
        if (kt == qb) {
            const int r0 = warp * 16 + gid;
            #pragma unroll
            for (int nt = 0; nt < 8; nt++) {
                const int c = nt * 8 + 2 * tig;
                if (c > r0)         s[nt][0] = -1e30f;
                if (c + 1 > r0)     s[nt][1] = -1e30f;
                if (c > r0 + 8)     s[nt][2] = -1e30f;
                if (c + 1 > r0 + 8) s[nt][3] = -1e30f;
            }
        }

        float mx0 = -1e30f, mx1 = -1e30f;
        #pragma unroll
        for (int nt = 0; nt < 8; nt++) {
            mx0 = fmaxf(mx0, fmaxf(s[nt][0], s[nt][1]));
            mx1 = fmaxf(mx1, fmaxf(s[nt][2], s[nt][3]));
        }
        mx0 = fmaxf(mx0, __shfl_xor_sync(0xffffffffu, mx0, 1));
        mx0 = fmaxf(mx0, __shfl_xor_sync(0xffffffffu, mx0, 2));
        mx1 = fmaxf(mx1, __shfl_xor_sync(0xffffffffu, mx1, 1));
        mx1 = fmaxf(mx1, __shfl_xor_sync(0xffffffffu, mx1, 2));

        const float nm0 = fmaxf(m0v, mx0);
        const float nm1 = fmaxf(m1v, mx1);
        const float al0 = __expf(m0v - nm0);
        const float al1 = __expf(m1v - nm1);
        m0v = nm0; m1v = nm1;

        float rs0 = 0.f, rs1 = 0.f;
        #pragma unroll
        for (int nt = 0; nt < 8; nt++) {
            const float p0 = __expf(s[nt][0] - m0v);
            const float p1 = __expf(s[nt][1] - m0v);
            const float p2 = __expf(s[nt][2] - m1v);
            const float p3 = __expf(s[nt][3] - m1v);
            rs0 += p0 + p1;
            rs1 += p2 + p3;
            Pw[gid * APIT + nt * 4 + tig]       = f2h2(p0, p1);
            Pw[(gid + 8) * APIT + nt * 4 + tig] = f2h2(p2, p3);
        }
        rs0 += __shfl_xor_sync(0xffffffffu, rs0, 1);
        rs0 += __shfl_xor_sync(0xffffffffu, rs0, 2);
        rs1 += __shfl_xor_sync(0xffffffffu, rs1, 1);
        rs1 += __shfl_xor_sync(0xffffffffu, rs1, 2);
        l0 = l0 * al0 + rs0;
        l1 = l1 * al1 + rs1;

        #pragma unroll
        for (int nt = 0; nt < 8; nt++) {
            o[nt][0] *= al0; o[nt][1] *= al0;
            o[nt][2] *= al1; o[nt][3] *= al1;
        }

        __syncwarp();   // P visible across lanes

        // O += P @ V. A-frags via ldsm4 on Pw, B-frags via ldsm4t on Vs.
        #pragma unroll
        for (int kcv = 0; kcv < 4; kcv++) {
            unsigned af[4];
            {
                const uint32_t a = sb +
                    (pwoff + ((mat & 1) * 8 + mj) * APIT +
                     kcv * 8 + (mat >> 1) * 4) * 4;
                ldsm4(af, a);
            }
            #pragma unroll
            for (int ntp = 0; ntp < 4; ntp++) {
                const uint32_t a = sb +
                    ((2 + cur) * KVBUF + (kcv * 16 + (mat & 1) * 8 + mj) * APIT +
                     ntp * 8 + (mat >> 1) * 4) * 4;
                unsigned r[4];
                ldsm4t(r, a);
                mma_f16(o[2 * ntp],     af, r);
                mma_f16(o[2 * ntp + 1], af, r + 2);
            }
        }
        __syncthreads();
    }

    // Epilogue: O /= l, scatter fp16 to ctx
    const float il0 = 1.0f / l0;
    const float il1 = 1.0f / l1;
    __half* ob = g_ctx + (size_t)(b * SEQ + q0 + warp * 16) * DMODEL + h * 64;
    #pragma unroll
    for (int nt = 0; nt < 8; nt++) {
        const int col = nt * 8 + 2 * tig;
        *(unsigned*)&ob[gid * DMODEL + col] =
            f2h2(o[nt][0] * il0, o[nt][1] * il0);
        *(unsigned*)&ob[(gid + 8) * DMODEL + col] =
            f2h2(o[nt][2] * il1, o[nt][3] * il1);
    }
}

// ---------------------------------------------------------------------------
extern "C" void kernel_launch(void* const* d_in, const int* in_sizes, int n_in,
                              void* d_out, int out_size)
{
    const float* x  = (const float*)d_in[0];
    const float* Wq = (const float*)d_in[1];
    const float* Wk = (const float*)d_in[2];
    const float* Wv = (const float*)d_in[3];
    const float* Wo = (const float*)d_in[4];
    float* out = (float*)d_out;

    cudaFuncSetAttribute(gemm_kernel<0>,
                         cudaFuncAttributeMaxDynamicSharedMemorySize, GEMM_SMEM);
    cudaFuncSetAttribute(gemm_kernel<1>,
                         cudaFuncAttributeMaxDynamicSharedMemorySize, GEMM_SMEM);
    cudaFuncSetAttribute(attn_mma_kernel,
                         cudaFuncAttributeMaxDynamicSharedMemorySize,
                         ATTN_SMEM_BYTES);

    rope_table_kernel<<<256, 256>>>();
    convert_kernel<<<(NX2 + 4 * NW2) / 256, 256>>>(x, Wq, Wk, Wv, Wo);

    dim3 gq(DMODEL / 128, NQ / 128, 3);
    gemm_kernel<0><<<gq, 256, GEMM_SMEM>>>(0);

    dim3 ga(SEQ / 64, NHEADS, BATCH);
    attn_mma_kernel<<<ga, 128, ATTN_SMEM_BYTES>>>();

    dim3 go(DMODEL / 128, NQ / 128, 1);
    gemm_kernel<1><<<go, 256, GEMM_SMEM>>>(out);
}